// round 1
// baseline (speedup 1.0000x reference)
#include <cuda_runtime.h>
#include <cuda_bf16.h>
#include <math.h>

// ---------------------------------------------------------------------------
// Model constants
// ---------------------------------------------------------------------------
#define B_      2
#define S_      2048
#define T_      (B_ * S_)        // 4096 tokens
#define DIM_    1024
#define NH_     16
#define HD_     64
#define NL_     4
#define HFF_    2816
#define VOCAB_  32000

// ---------------------------------------------------------------------------
// Scratch (static device globals: allocation-free per harness rules)
// ---------------------------------------------------------------------------
__device__ float g_h [T_ * DIM_];
__device__ float g_xn[T_ * DIM_];
__device__ float g_q [T_ * DIM_];
__device__ float g_k [T_ * DIM_];
__device__ float g_v [T_ * DIM_];
__device__ float g_o [T_ * DIM_];
__device__ float g_g1[T_ * HFF_];
__device__ float g_g3[T_ * HFF_];

// ---------------------------------------------------------------------------
// Embedding gather: h[t,:] = tok_emb[tokens[t],:]
// ---------------------------------------------------------------------------
__global__ void embed_kernel(const int* __restrict__ tokens,
                             const float* __restrict__ emb,
                             float* __restrict__ h) {
    int t = blockIdx.x;
    int tok = tokens[t];
    const float* src = emb + (size_t)tok * DIM_;
    float* dst = h + (size_t)t * DIM_;
    for (int i = threadIdx.x; i < DIM_; i += blockDim.x) dst[i] = src[i];
}

// ---------------------------------------------------------------------------
// RMSNorm: y = x * rsqrt(mean(x^2)+eps) * w     (one block per token)
// ---------------------------------------------------------------------------
__global__ void rmsnorm_kernel(const float* __restrict__ x,
                               const float* __restrict__ w,
                               float* __restrict__ y) {
    int t = blockIdx.x;
    const float* xr = x + (size_t)t * DIM_;
    float* yr = y + (size_t)t * DIM_;
    float ss = 0.f;
    #pragma unroll
    for (int i = threadIdx.x; i < DIM_; i += 256) { float v = xr[i]; ss += v * v; }
    #pragma unroll
    for (int off = 16; off > 0; off >>= 1)
        ss += __shfl_xor_sync(0xffffffffu, ss, off);
    __shared__ float red[8];
    if ((threadIdx.x & 31) == 0) red[threadIdx.x >> 5] = ss;
    __syncthreads();
    float tot = 0.f;
    #pragma unroll
    for (int i = 0; i < 8; i++) tot += red[i];
    float sc = rsqrtf(tot * (1.0f / DIM_) + 1e-5f);
    #pragma unroll
    for (int i = threadIdx.x; i < DIM_; i += 256) yr[i] = xr[i] * sc * w[i];
}

// ---------------------------------------------------------------------------
// SGEMM NT:  C[M,N] (+)= A[M,K] * B[N,K]^T
// 128x128x8 tile, 256 threads, 8x8 micro-tile per thread.
// All call sites have M%128==0, N%128==0, K%8==0 -> no bounds checks.
// ---------------------------------------------------------------------------
template<bool ACC>
__global__ __launch_bounds__(256, 2)
void sgemm_nt(const float* __restrict__ A, const float* __restrict__ B,
              float* __restrict__ C, int M, int N, int K) {
    __shared__ float As[8][132];
    __shared__ float Bs[8][132];

    int tid = threadIdx.x;
    int m0 = blockIdx.y * 128;
    int n0 = blockIdx.x * 128;
    int tx = tid & 15;          // 0..15 -> n
    int ty = tid >> 4;          // 0..15 -> m

    int arow = tid >> 1;        // 0..127
    int ak   = (tid & 1) * 4;   // 0 or 4

    const float* Aptr = A + (size_t)(m0 + arow) * K + ak;
    const float* Bptr = B + (size_t)(n0 + arow) * K + ak;

    float acc[8][8];
    #pragma unroll
    for (int i = 0; i < 8; i++)
        #pragma unroll
        for (int j = 0; j < 8; j++) acc[i][j] = 0.f;

    for (int k0 = 0; k0 < K; k0 += 8) {
        float4 av = *(const float4*)(Aptr + k0);
        float4 bv = *(const float4*)(Bptr + k0);
        __syncthreads();
        As[ak + 0][arow] = av.x; As[ak + 1][arow] = av.y;
        As[ak + 2][arow] = av.z; As[ak + 3][arow] = av.w;
        Bs[ak + 0][arow] = bv.x; Bs[ak + 1][arow] = bv.y;
        Bs[ak + 2][arow] = bv.z; Bs[ak + 3][arow] = bv.w;
        __syncthreads();
        #pragma unroll
        for (int kk = 0; kk < 8; kk++) {
            float a[8], b[8];
            *(float4*)(a)     = *(const float4*)&As[kk][ty * 8];
            *(float4*)(a + 4) = *(const float4*)&As[kk][ty * 8 + 4];
            *(float4*)(b)     = *(const float4*)&Bs[kk][tx * 8];
            *(float4*)(b + 4) = *(const float4*)&Bs[kk][tx * 8 + 4];
            #pragma unroll
            for (int i = 0; i < 8; i++)
                #pragma unroll
                for (int j = 0; j < 8; j++)
                    acc[i][j] += a[i] * b[j];
        }
    }

    #pragma unroll
    for (int i = 0; i < 8; i++) {
        float* crow = C + (size_t)(m0 + ty * 8 + i) * N + n0 + tx * 8;
        #pragma unroll
        for (int j = 0; j < 8; j++)
            crow[j] = ACC ? (crow[j] + acc[i][j]) : acc[i][j];
    }
}

// ---------------------------------------------------------------------------
// RoPE applied in-place to q and k. One thread per (token, pair).
// layout: x[t*1024 + h*64 + 2i/(2i+1)], pair index p = h*32 + i  -> offset p*2
// ---------------------------------------------------------------------------
__global__ void rope_kernel(float* __restrict__ q, float* __restrict__ k) {
    int idx = blockIdx.x * blockDim.x + threadIdx.x;   // T_*512 threads
    int t = idx >> 9;
    int p = idx & 511;
    int i = p & 31;
    int s = t & (S_ - 1);
    // inv_freq = theta^(-2i/64)
    float inv = expf(-(float)(2 * i) * (1.0f / HD_) * 9.210340371976184f); // ln(10000)
    float ang = (float)s * inv;
    float sn, cs;
    sincosf(ang, &sn, &cs);
    size_t off = (size_t)t * DIM_ + p * 2;
    float x0 = q[off], x1 = q[off + 1];
    q[off]     = x0 * cs - x1 * sn;
    q[off + 1] = x0 * sn + x1 * cs;
    x0 = k[off]; x1 = k[off + 1];
    k[off]     = x0 * cs - x1 * sn;
    k[off + 1] = x0 * sn + x1 * cs;
}

// ---------------------------------------------------------------------------
// Flash-style causal attention (fp32). Grid: (S/32, NH, B), 256 threads.
// Each block: 32 queries of one (b,h). Streams 64-key tiles with online softmax.
// Thread mapping: r = tid/8 (query row), c8 = tid%8; thread owns keys/cols
// {c8 + 8j} (strided -> conflict-free smem access).
// ---------------------------------------------------------------------------
__global__ __launch_bounds__(256)
void attn_kernel(const float* __restrict__ q, const float* __restrict__ k,
                 const float* __restrict__ v, float* __restrict__ o) {
    __shared__ float Qs[32][68];
    __shared__ float Ks[64][68];
    __shared__ float Vs[64][68];

    int q0 = blockIdx.x * 32;
    int h  = blockIdx.y;
    int b  = blockIdx.z;
    int tid = threadIdx.x;
    const float scale = 0.125f;   // 1/sqrt(64)

    size_t base = ((size_t)b * S_) * DIM_ + (size_t)h * HD_;

    // load + pre-scale Q tile
    for (int idx = tid; idx < 32 * 64; idx += 256) {
        int r = idx >> 6, d = idx & 63;
        Qs[r][d] = q[base + (size_t)(q0 + r) * DIM_ + d] * scale;
    }

    int r  = tid >> 3;
    int c8 = tid & 7;

    float m = -INFINITY, l = 0.f;
    float acc[8];
    #pragma unroll
    for (int j = 0; j < 8; j++) acc[j] = 0.f;

    int nkt = (q0 + 31) / 64 + 1;
    for (int kt = 0; kt < nkt; kt++) {
        int k0 = kt * 64;
        __syncthreads();
        for (int idx = tid; idx < 64 * 64; idx += 256) {
            int rr = idx >> 6, d = idx & 63;
            size_t g = base + (size_t)(k0 + rr) * DIM_ + d;
            Ks[rr][d] = k[g];
            Vs[rr][d] = v[g];
        }
        __syncthreads();

        // scores for this thread's 8 keys
        float s[8];
        #pragma unroll
        for (int j = 0; j < 8; j++) s[j] = 0.f;
        #pragma unroll 8
        for (int d = 0; d < 64; d++) {
            float qd = Qs[r][d];
            #pragma unroll
            for (int j = 0; j < 8; j++) s[j] += qd * Ks[c8 + 8 * j][d];
        }

        // causal mask + row max
        float tm = -INFINITY;
        #pragma unroll
        for (int j = 0; j < 8; j++) {
            if (k0 + c8 + 8 * j > q0 + r) s[j] = -INFINITY;
            tm = fmaxf(tm, s[j]);
        }
        #pragma unroll
        for (int off = 1; off < 8; off <<= 1)
            tm = fmaxf(tm, __shfl_xor_sync(0xffffffffu, tm, off));

        float mn = fmaxf(m, tm);
        float corr = __expf(m - mn);      // m=-inf first tile -> 0
        float p[8];
        float ls = 0.f;
        #pragma unroll
        for (int j = 0; j < 8; j++) { p[j] = __expf(s[j] - mn); ls += p[j]; }
        #pragma unroll
        for (int off = 1; off < 8; off <<= 1)
            ls += __shfl_xor_sync(0xffffffffu, ls, off);

        l = l * corr + ls;
        m = mn;
        #pragma unroll
        for (int j = 0; j < 8; j++) acc[j] *= corr;

        // PV: broadcast p across the 8-lane row group via shfl (width=8)
        #pragma unroll 8
        for (int kk = 0; kk < 64; kk++) {
            float pk = __shfl_sync(0xffffffffu, p[kk >> 3], kk & 7, 8);
            #pragma unroll
            for (int j = 0; j < 8; j++) acc[j] += pk * Vs[kk][c8 + 8 * j];
        }
    }

    float invl = 1.f / l;
    size_t obase = base + (size_t)(q0 + r) * DIM_;
    #pragma unroll
    for (int j = 0; j < 8; j++) o[obase + c8 + 8 * j] = acc[j] * invl;
}

// ---------------------------------------------------------------------------
// SwiGLU elementwise: g1 = silu(g1) * g3
// ---------------------------------------------------------------------------
__global__ void silu_mul_kernel(float* __restrict__ g1, const float* __restrict__ g3) {
    int idx = blockIdx.x * blockDim.x + threadIdx.x;
    float a = g1[idx];
    float b = g3[idx];
    g1[idx] = a / (1.f + __expf(-a)) * b;
}

// ---------------------------------------------------------------------------
// Host orchestration
// ---------------------------------------------------------------------------
extern "C" void kernel_launch(void* const* d_in, const int* in_sizes, int n_in,
                              void* d_out, int out_size) {
    const int*   tokens      = (const int*)  d_in[0];
    const float* tok_emb     = (const float*)d_in[1];
    const float* wq          = (const float*)d_in[2];
    const float* wk          = (const float*)d_in[3];
    const float* wv          = (const float*)d_in[4];
    const float* wo          = (const float*)d_in[5];
    const float* w1          = (const float*)d_in[6];
    const float* w2          = (const float*)d_in[7];
    const float* w3          = (const float*)d_in[8];
    const float* attn_norm_w = (const float*)d_in[9];
    const float* ffn_norm_w  = (const float*)d_in[10];
    const float* norm_w      = (const float*)d_in[11];
    const float* out_w       = (const float*)d_in[12];

    float *h, *xn, *q, *k, *v, *o, *g1, *g3;
    cudaGetSymbolAddress((void**)&h,  g_h);
    cudaGetSymbolAddress((void**)&xn, g_xn);
    cudaGetSymbolAddress((void**)&q,  g_q);
    cudaGetSymbolAddress((void**)&k,  g_k);
    cudaGetSymbolAddress((void**)&v,  g_v);
    cudaGetSymbolAddress((void**)&o,  g_o);
    cudaGetSymbolAddress((void**)&g1, g_g1);
    cudaGetSymbolAddress((void**)&g3, g_g3);

    embed_kernel<<<T_, 256>>>(tokens, tok_emb, h);

    dim3 gDD (DIM_  / 128, T_ / 128);   // N=1024
    dim3 gDF (HFF_  / 128, T_ / 128);   // N=2816
    dim3 gDV (VOCAB_/ 128, T_ / 128);   // N=32000

    for (int l = 0; l < NL_; l++) {
        const float* wq_l = wq + (size_t)l * DIM_ * DIM_;
        const float* wk_l = wk + (size_t)l * DIM_ * DIM_;
        const float* wv_l = wv + (size_t)l * DIM_ * DIM_;
        const float* wo_l = wo + (size_t)l * DIM_ * DIM_;
        const float* w1_l = w1 + (size_t)l * HFF_ * DIM_;
        const float* w2_l = w2 + (size_t)l * DIM_ * HFF_;
        const float* w3_l = w3 + (size_t)l * HFF_ * DIM_;

        // attention block
        rmsnorm_kernel<<<T_, 256>>>(h, attn_norm_w + (size_t)l * DIM_, xn);
        sgemm_nt<false><<<gDD, 256>>>(xn, wq_l, q, T_, DIM_, DIM_);
        sgemm_nt<false><<<gDD, 256>>>(xn, wk_l, k, T_, DIM_, DIM_);
        sgemm_nt<false><<<gDD, 256>>>(xn, wv_l, v, T_, DIM_, DIM_);
        rope_kernel<<<(T_ * 512) / 256, 256>>>(q, k);
        attn_kernel<<<dim3(S_ / 32, NH_, B_), 256>>>(q, k, v, o);
        sgemm_nt<true ><<<gDD, 256>>>(o, wo_l, h, T_, DIM_, DIM_);   // residual add

        // FFN block
        rmsnorm_kernel<<<T_, 256>>>(h, ffn_norm_w + (size_t)l * DIM_, xn);
        sgemm_nt<false><<<gDF, 256>>>(xn, w1_l, g1, T_, HFF_, DIM_);
        sgemm_nt<false><<<gDF, 256>>>(xn, w3_l, g3, T_, HFF_, DIM_);
        silu_mul_kernel<<<(T_ * HFF_) / 256, 256>>>(g1, g3);
        sgemm_nt<true ><<<gDD, 256>>>(g1, w2_l, h, T_, DIM_, HFF_);  // residual add
    }

    rmsnorm_kernel<<<T_, 256>>>(h, norm_w, xn);
    sgemm_nt<false><<<gDV, 256>>>(xn, out_w, (float*)d_out, T_, VOCAB_, DIM_);
}

// round 3
// speedup vs baseline: 1.2399x; 1.2399x over previous
#include <cuda_runtime.h>
#include <cuda_bf16.h>
#include <math.h>
#include <stdint.h>

// ---------------------------------------------------------------------------
// Model constants
// ---------------------------------------------------------------------------
#define B_      2
#define S_      2048
#define T_      (B_ * S_)        // 4096 tokens
#define DIM_    1024
#define NH_     16
#define HD_     64
#define NL_     4
#define HFF_    2816
#define VOCAB_  32000

// ---------------------------------------------------------------------------
// Scratch (static device globals: allocation-free per harness rules)
// ---------------------------------------------------------------------------
__device__ float g_h [T_ * DIM_];
__device__ float g_xn[T_ * DIM_];
__device__ float g_q [T_ * DIM_];
__device__ float g_k [T_ * DIM_];
__device__ float g_v [T_ * DIM_];
__device__ float g_o [T_ * DIM_];
__device__ float g_g1[T_ * HFF_];
__device__ float g_g3[T_ * HFF_];

// ---------------------------------------------------------------------------
// Embedding gather
// ---------------------------------------------------------------------------
__global__ void embed_kernel(const int* __restrict__ tokens,
                             const float* __restrict__ emb,
                             float* __restrict__ h) {
    int t = blockIdx.x;
    int tok = tokens[t];
    const float* src = emb + (size_t)tok * DIM_;
    float* dst = h + (size_t)t * DIM_;
    for (int i = threadIdx.x; i < DIM_; i += blockDim.x) dst[i] = src[i];
}

// ---------------------------------------------------------------------------
// RMSNorm
// ---------------------------------------------------------------------------
__global__ void rmsnorm_kernel(const float* __restrict__ x,
                               const float* __restrict__ w,
                               float* __restrict__ y) {
    int t = blockIdx.x;
    const float* xr = x + (size_t)t * DIM_;
    float* yr = y + (size_t)t * DIM_;
    float ss = 0.f;
    #pragma unroll
    for (int i = threadIdx.x; i < DIM_; i += 256) { float v = xr[i]; ss += v * v; }
    #pragma unroll
    for (int off = 16; off > 0; off >>= 1)
        ss += __shfl_xor_sync(0xffffffffu, ss, off);
    __shared__ float red[8];
    if ((threadIdx.x & 31) == 0) red[threadIdx.x >> 5] = ss;
    __syncthreads();
    float tot = 0.f;
    #pragma unroll
    for (int i = 0; i < 8; i++) tot += red[i];
    float sc = rsqrtf(tot * (1.0f / DIM_) + 1e-5f);
    #pragma unroll
    for (int i = threadIdx.x; i < DIM_; i += 256) yr[i] = xr[i] * sc * w[i];
}

// ---------------------------------------------------------------------------
// tf32 helpers
// ---------------------------------------------------------------------------
__device__ __forceinline__ float to_tf32(float x) {
    uint32_t u;
    asm("cvt.rna.tf32.f32 %0, %1;" : "=r"(u) : "f"(x));
    return __uint_as_float(u);
}

// split x into hi (tf32) + lo (tf32 of residual); x ~= hi + lo to ~22 bits
__device__ __forceinline__ void st4_split(float* ph, float* pl, float4 v) {
    float h0 = to_tf32(v.x), h1 = to_tf32(v.y), h2 = to_tf32(v.z), h3 = to_tf32(v.w);
    ph[0] = h0; ph[1] = h1; ph[2] = h2; ph[3] = h3;
    pl[0] = to_tf32(v.x - h0); pl[1] = to_tf32(v.y - h1);
    pl[2] = to_tf32(v.z - h2); pl[3] = to_tf32(v.w - h3);
}

__device__ __forceinline__ void mma_tf32(float* c, const uint32_t* a, const uint32_t* b) {
    asm volatile(
        "mma.sync.aligned.m16n8k8.row.col.f32.tf32.tf32.f32 "
        "{%0,%1,%2,%3}, {%4,%5,%6,%7}, {%8,%9}, {%0,%1,%2,%3};"
        : "+f"(c[0]), "+f"(c[1]), "+f"(c[2]), "+f"(c[3])
        : "r"(a[0]), "r"(a[1]), "r"(a[2]), "r"(a[3]),
          "r"(b[0]), "r"(b[1]));
}

// ---------------------------------------------------------------------------
// 3xTF32 tensor-core GEMM NT:  C[M,N] (+)= A[M,K] * B[N,K]^T  (fp32-accurate)
// 128x128 CTA tile, 8 warps (4m x 2n), warp tile 32x64, K staged 16,
// double-buffered dynamic smem holding hi/lo tf32 planes (stride 20,
// conflict-free fragment LDS). Per product: hi*hi + hi*lo + lo*hi.
// All call sites: M%128==0, N%128==0, K%16==0.
// ---------------------------------------------------------------------------
#define PLANE_ (128 * 20)
#define GSMEM_BYTES_ (2 * 4 * PLANE_ * 4)   // 2 bufs x 4 planes x 2560 floats

template<bool ACC>
__global__ __launch_bounds__(256, 1)
void tgemm_nt(const float* __restrict__ A, const float* __restrict__ B,
              float* __restrict__ C, int M, int N, int K) {
    extern __shared__ float sm[];
    // planes per buffer: 0=A_hi 1=A_lo 2=B_hi 3=B_lo
    auto plane = [&](int buf, int which) -> float* {
        return sm + (buf * 4 + which) * PLANE_;
    };

    int tid  = threadIdx.x;
    int m0   = blockIdx.y * 128;
    int n0   = blockIdx.x * 128;
    int wid  = tid >> 5;
    int lane = tid & 31;
    int wm = (wid >> 1) * 32;   // 4 warps along m
    int wn = (wid & 1) * 64;    // 2 warps along n
    int lr = lane >> 2;         // 0..7
    int lc = lane & 3;          // 0..3

    // staging: each thread loads 2 float4 per operand tile (128 x 16)
    int srow = tid >> 2;          // 0..63
    int scol = (tid & 3) * 4;     // 0,4,8,12
    const float* Ag = A + (size_t)(m0 + srow) * K + scol;
    const float* Bg = B + (size_t)(n0 + srow) * K + scol;
    size_t rstep = (size_t)64 * K;

    float4 av0 = *(const float4*)(Ag);
    float4 av1 = *(const float4*)(Ag + rstep);
    float4 bv0 = *(const float4*)(Bg);
    float4 bv1 = *(const float4*)(Bg + rstep);

    float acc[2][8][4];
    #pragma unroll
    for (int i = 0; i < 2; i++)
        #pragma unroll
        for (int j = 0; j < 8; j++)
            #pragma unroll
            for (int t = 0; t < 4; t++) acc[i][j][t] = 0.f;

    int o0 = srow * 20 + scol;
    int o1 = (srow + 64) * 20 + scol;
    st4_split(plane(0,0) + o0, plane(0,1) + o0, av0);
    st4_split(plane(0,0) + o1, plane(0,1) + o1, av1);
    st4_split(plane(0,2) + o0, plane(0,3) + o0, bv0);
    st4_split(plane(0,2) + o1, plane(0,3) + o1, bv1);

    int buf = 0;
    for (int k0 = 0; k0 < K; k0 += 16) {
        __syncthreads();
        bool more = (k0 + 16) < K;
        if (more) {
            av0 = *(const float4*)(Ag + k0 + 16);
            av1 = *(const float4*)(Ag + rstep + k0 + 16);
            bv0 = *(const float4*)(Bg + k0 + 16);
            bv1 = *(const float4*)(Bg + rstep + k0 + 16);
        }

        const float* Ah = plane(buf, 0);
        const float* Al = plane(buf, 1);
        const float* Bh = plane(buf, 2);
        const float* Bl = plane(buf, 3);

        #pragma unroll
        for (int ks = 0; ks < 2; ks++) {
            int kk = ks * 8;
            uint32_t ah[2][4], al[2][4], bh[8][2], bl[8][2];
            #pragma unroll
            for (int mf = 0; mf < 2; mf++) {
                int r0 = (wm + mf * 16 + lr) * 20 + kk + lc;
                int r1 = r0 + 8 * 20;
                ah[mf][0] = __float_as_uint(Ah[r0]);
                ah[mf][1] = __float_as_uint(Ah[r1]);
                ah[mf][2] = __float_as_uint(Ah[r0 + 4]);
                ah[mf][3] = __float_as_uint(Ah[r1 + 4]);
                al[mf][0] = __float_as_uint(Al[r0]);
                al[mf][1] = __float_as_uint(Al[r1]);
                al[mf][2] = __float_as_uint(Al[r0 + 4]);
                al[mf][3] = __float_as_uint(Al[r1 + 4]);
            }
            #pragma unroll
            for (int nf = 0; nf < 8; nf++) {
                int c0 = (wn + nf * 8 + lr) * 20 + kk + lc;
                bh[nf][0] = __float_as_uint(Bh[c0]);
                bh[nf][1] = __float_as_uint(Bh[c0 + 4]);
                bl[nf][0] = __float_as_uint(Bl[c0]);
                bl[nf][1] = __float_as_uint(Bl[c0 + 4]);
            }
            #pragma unroll
            for (int mf = 0; mf < 2; mf++)
                #pragma unroll
                for (int nf = 0; nf < 8; nf++) {
                    mma_tf32(acc[mf][nf], al[mf], bh[nf]);
                    mma_tf32(acc[mf][nf], ah[mf], bl[nf]);
                    mma_tf32(acc[mf][nf], ah[mf], bh[nf]);
                }
        }

        if (more) {
            int nb = buf ^ 1;
            st4_split(plane(nb,0) + o0, plane(nb,1) + o0, av0);
            st4_split(plane(nb,0) + o1, plane(nb,1) + o1, av1);
            st4_split(plane(nb,2) + o0, plane(nb,3) + o0, bv0);
            st4_split(plane(nb,2) + o1, plane(nb,3) + o1, bv1);
            buf = nb;
        }
    }

    // epilogue
    #pragma unroll
    for (int mf = 0; mf < 2; mf++) {
        #pragma unroll
        for (int nf = 0; nf < 8; nf++) {
            int row = m0 + wm + mf * 16 + lr;
            int col = n0 + wn + nf * 8 + 2 * lc;
            float* p0 = C + (size_t)row * N + col;
            float* p1 = p0 + (size_t)8 * N;
            if (ACC) {
                float2 q0 = *(float2*)p0;
                float2 q1 = *(float2*)p1;
                q0.x += acc[mf][nf][0]; q0.y += acc[mf][nf][1];
                q1.x += acc[mf][nf][2]; q1.y += acc[mf][nf][3];
                *(float2*)p0 = q0;
                *(float2*)p1 = q1;
            } else {
                *(float2*)p0 = make_float2(acc[mf][nf][0], acc[mf][nf][1]);
                *(float2*)p1 = make_float2(acc[mf][nf][2], acc[mf][nf][3]);
            }
        }
    }
}

// ---------------------------------------------------------------------------
// RoPE applied in-place to q and k
// ---------------------------------------------------------------------------
__global__ void rope_kernel(float* __restrict__ q, float* __restrict__ k) {
    int idx = blockIdx.x * blockDim.x + threadIdx.x;
    int t = idx >> 9;
    int p = idx & 511;
    int i = p & 31;
    int s = t & (S_ - 1);
    float inv = expf(-(float)(2 * i) * (1.0f / HD_) * 9.210340371976184f);
    float ang = (float)s * inv;
    float sn, cs;
    sincosf(ang, &sn, &cs);
    size_t off = (size_t)t * DIM_ + p * 2;
    float x0 = q[off], x1 = q[off + 1];
    q[off]     = x0 * cs - x1 * sn;
    q[off + 1] = x0 * sn + x1 * cs;
    x0 = k[off]; x1 = k[off + 1];
    k[off]     = x0 * cs - x1 * sn;
    k[off + 1] = x0 * sn + x1 * cs;
}

// ---------------------------------------------------------------------------
// Flash-style causal attention (fp32)
// ---------------------------------------------------------------------------
__global__ __launch_bounds__(256)
void attn_kernel(const float* __restrict__ q, const float* __restrict__ k,
                 const float* __restrict__ v, float* __restrict__ o) {
    __shared__ float Qs[32][68];
    __shared__ float Ks[64][68];
    __shared__ float Vs[64][68];

    int q0 = blockIdx.x * 32;
    int h  = blockIdx.y;
    int b  = blockIdx.z;
    int tid = threadIdx.x;
    const float scale = 0.125f;

    size_t base = ((size_t)b * S_) * DIM_ + (size_t)h * HD_;

    for (int idx = tid; idx < 32 * 64; idx += 256) {
        int r = idx >> 6, d = idx & 63;
        Qs[r][d] = q[base + (size_t)(q0 + r) * DIM_ + d] * scale;
    }

    int r  = tid >> 3;
    int c8 = tid & 7;

    float m = -INFINITY, l = 0.f;
    float acc[8];
    #pragma unroll
    for (int j = 0; j < 8; j++) acc[j] = 0.f;

    int nkt = (q0 + 31) / 64 + 1;
    for (int kt = 0; kt < nkt; kt++) {
        int k0 = kt * 64;
        __syncthreads();
        for (int idx = tid; idx < 64 * 64; idx += 256) {
            int rr = idx >> 6, d = idx & 63;
            size_t g = base + (size_t)(k0 + rr) * DIM_ + d;
            Ks[rr][d] = k[g];
            Vs[rr][d] = v[g];
        }
        __syncthreads();

        float s[8];
        #pragma unroll
        for (int j = 0; j < 8; j++) s[j] = 0.f;
        #pragma unroll 8
        for (int d = 0; d < 64; d++) {
            float qd = Qs[r][d];
            #pragma unroll
            for (int j = 0; j < 8; j++) s[j] += qd * Ks[c8 + 8 * j][d];
        }

        float tm = -INFINITY;
        #pragma unroll
        for (int j = 0; j < 8; j++) {
            if (k0 + c8 + 8 * j > q0 + r) s[j] = -INFINITY;
            tm = fmaxf(tm, s[j]);
        }
        #pragma unroll
        for (int off = 1; off < 8; off <<= 1)
            tm = fmaxf(tm, __shfl_xor_sync(0xffffffffu, tm, off));

        float mn = fmaxf(m, tm);
        float corr = __expf(m - mn);
        float p[8];
        float ls = 0.f;
        #pragma unroll
        for (int j = 0; j < 8; j++) { p[j] = __expf(s[j] - mn); ls += p[j]; }
        #pragma unroll
        for (int off = 1; off < 8; off <<= 1)
            ls += __shfl_xor_sync(0xffffffffu, ls, off);

        l = l * corr + ls;
        m = mn;
        #pragma unroll
        for (int j = 0; j < 8; j++) acc[j] *= corr;

        #pragma unroll 8
        for (int kk = 0; kk < 64; kk++) {
            float pk = __shfl_sync(0xffffffffu, p[kk >> 3], kk & 7, 8);
            #pragma unroll
            for (int j = 0; j < 8; j++) acc[j] += pk * Vs[kk][c8 + 8 * j];
        }
    }

    float invl = 1.f / l;
    size_t obase = base + (size_t)(q0 + r) * DIM_;
    #pragma unroll
    for (int j = 0; j < 8; j++) o[obase + c8 + 8 * j] = acc[j] * invl;
}

// ---------------------------------------------------------------------------
// SwiGLU elementwise
// ---------------------------------------------------------------------------
__global__ void silu_mul_kernel(float* __restrict__ g1, const float* __restrict__ g3) {
    int idx = blockIdx.x * blockDim.x + threadIdx.x;
    float a = g1[idx];
    float b = g3[idx];
    g1[idx] = a / (1.f + __expf(-a)) * b;
}

// ---------------------------------------------------------------------------
// Host orchestration
// ---------------------------------------------------------------------------
extern "C" void kernel_launch(void* const* d_in, const int* in_sizes, int n_in,
                              void* d_out, int out_size) {
    const int*   tokens      = (const int*)  d_in[0];
    const float* tok_emb     = (const float*)d_in[1];
    const float* wq          = (const float*)d_in[2];
    const float* wk          = (const float*)d_in[3];
    const float* wv          = (const float*)d_in[4];
    const float* wo          = (const float*)d_in[5];
    const float* w1          = (const float*)d_in[6];
    const float* w2          = (const float*)d_in[7];
    const float* w3          = (const float*)d_in[8];
    const float* attn_norm_w = (const float*)d_in[9];
    const float* ffn_norm_w  = (const float*)d_in[10];
    const float* norm_w      = (const float*)d_in[11];
    const float* out_w       = (const float*)d_in[12];

    float *h, *xn, *q, *k, *v, *o, *g1, *g3;
    cudaGetSymbolAddress((void**)&h,  g_h);
    cudaGetSymbolAddress((void**)&xn, g_xn);
    cudaGetSymbolAddress((void**)&q,  g_q);
    cudaGetSymbolAddress((void**)&k,  g_k);
    cudaGetSymbolAddress((void**)&v,  g_v);
    cudaGetSymbolAddress((void**)&o,  g_o);
    cudaGetSymbolAddress((void**)&g1, g_g1);
    cudaGetSymbolAddress((void**)&g3, g_g3);

    // opt-in to 80KB dynamic smem for the GEMM kernels (host-side, idempotent)
    cudaFuncSetAttribute(tgemm_nt<false>, cudaFuncAttributeMaxDynamicSharedMemorySize, GSMEM_BYTES_);
    cudaFuncSetAttribute(tgemm_nt<true >, cudaFuncAttributeMaxDynamicSharedMemorySize, GSMEM_BYTES_);

    embed_kernel<<<T_, 256>>>(tokens, tok_emb, h);

    dim3 gDD (DIM_   / 128, T_ / 128);
    dim3 gDF (HFF_   / 128, T_ / 128);
    dim3 gDV (VOCAB_ / 128, T_ / 128);

    for (int l = 0; l < NL_; l++) {
        const float* wq_l = wq + (size_t)l * DIM_ * DIM_;
        const float* wk_l = wk + (size_t)l * DIM_ * DIM_;
        const float* wv_l = wv + (size_t)l * DIM_ * DIM_;
        const float* wo_l = wo + (size_t)l * DIM_ * DIM_;
        const float* w1_l = w1 + (size_t)l * HFF_ * DIM_;
        const float* w2_l = w2 + (size_t)l * DIM_ * HFF_;
        const float* w3_l = w3 + (size_t)l * HFF_ * DIM_;

        rmsnorm_kernel<<<T_, 256>>>(h, attn_norm_w + (size_t)l * DIM_, xn);
        tgemm_nt<false><<<gDD, 256, GSMEM_BYTES_>>>(xn, wq_l, q, T_, DIM_, DIM_);
        tgemm_nt<false><<<gDD, 256, GSMEM_BYTES_>>>(xn, wk_l, k, T_, DIM_, DIM_);
        tgemm_nt<false><<<gDD, 256, GSMEM_BYTES_>>>(xn, wv_l, v, T_, DIM_, DIM_);
        rope_kernel<<<(T_ * 512) / 256, 256>>>(q, k);
        attn_kernel<<<dim3(S_ / 32, NH_, B_), 256>>>(q, k, v, o);
        tgemm_nt<true ><<<gDD, 256, GSMEM_BYTES_>>>(o, wo_l, h, T_, DIM_, DIM_);

        rmsnorm_kernel<<<T_, 256>>>(h, ffn_norm_w + (size_t)l * DIM_, xn);
        tgemm_nt<false><<<gDF, 256, GSMEM_BYTES_>>>(xn, w1_l, g1, T_, HFF_, DIM_);
        tgemm_nt<false><<<gDF, 256, GSMEM_BYTES_>>>(xn, w3_l, g3, T_, HFF_, DIM_);
        silu_mul_kernel<<<(T_ * HFF_) / 256, 256>>>(g1, g3);
        tgemm_nt<true ><<<gDD, 256, GSMEM_BYTES_>>>(g1, w2_l, h, T_, DIM_, HFF_);
    }

    rmsnorm_kernel<<<T_, 256>>>(h, norm_w, xn);
    tgemm_nt<false><<<gDV, 256, GSMEM_BYTES_>>>(xn, out_w, (float*)d_out, T_, VOCAB_, DIM_);
}

// round 4
// speedup vs baseline: 1.8583x; 1.4987x over previous
#include <cuda_runtime.h>
#include <cuda_bf16.h>
#include <math.h>
#include <stdint.h>

// ---------------------------------------------------------------------------
// Model constants
// ---------------------------------------------------------------------------
#define B_      2
#define S_      2048
#define T_      (B_ * S_)        // 4096 tokens
#define DIM_    1024
#define NH_     16
#define HD_     64
#define NL_     4
#define HFF_    2816
#define VOCAB_  32000

// ---------------------------------------------------------------------------
// Scratch (static device globals: allocation-free per harness rules)
// ---------------------------------------------------------------------------
__device__ float g_h [T_ * DIM_];
__device__ float g_xn[T_ * DIM_];
__device__ float g_q [T_ * DIM_];
__device__ float g_k [T_ * DIM_];
__device__ float g_v [T_ * DIM_];
__device__ float g_o [T_ * DIM_];
__device__ float g_g1[T_ * HFF_];
__device__ float g_g3[T_ * HFF_];

// ---------------------------------------------------------------------------
// Embedding gather
// ---------------------------------------------------------------------------
__global__ void embed_kernel(const int* __restrict__ tokens,
                             const float* __restrict__ emb,
                             float* __restrict__ h) {
    int t = blockIdx.x;
    int tok = tokens[t];
    const float* src = emb + (size_t)tok * DIM_;
    float* dst = h + (size_t)t * DIM_;
    for (int i = threadIdx.x; i < DIM_; i += blockDim.x) dst[i] = src[i];
}

// ---------------------------------------------------------------------------
// RMSNorm
// ---------------------------------------------------------------------------
__global__ void rmsnorm_kernel(const float* __restrict__ x,
                               const float* __restrict__ w,
                               float* __restrict__ y) {
    int t = blockIdx.x;
    const float* xr = x + (size_t)t * DIM_;
    float* yr = y + (size_t)t * DIM_;
    float ss = 0.f;
    #pragma unroll
    for (int i = threadIdx.x; i < DIM_; i += 256) { float v = xr[i]; ss += v * v; }
    #pragma unroll
    for (int off = 16; off > 0; off >>= 1)
        ss += __shfl_xor_sync(0xffffffffu, ss, off);
    __shared__ float red[8];
    if ((threadIdx.x & 31) == 0) red[threadIdx.x >> 5] = ss;
    __syncthreads();
    float tot = 0.f;
    #pragma unroll
    for (int i = 0; i < 8; i++) tot += red[i];
    float sc = rsqrtf(tot * (1.0f / DIM_) + 1e-5f);
    #pragma unroll
    for (int i = threadIdx.x; i < DIM_; i += 256) yr[i] = xr[i] * sc * w[i];
}

// ---------------------------------------------------------------------------
// bf16 split helpers: x ~= hi + lo with ~17 mantissa bits total
// ---------------------------------------------------------------------------
__device__ __forceinline__ uint32_t pack_bf16(__nv_bfloat16 a, __nv_bfloat16 b) {
    return (uint32_t)__bfloat16_as_ushort(a) |
           ((uint32_t)__bfloat16_as_ushort(b) << 16);
}

__device__ __forceinline__ void split4(float4 v, uint2& hi, uint2& lo) {
    __nv_bfloat16 h0 = __float2bfloat16(v.x);
    __nv_bfloat16 h1 = __float2bfloat16(v.y);
    __nv_bfloat16 h2 = __float2bfloat16(v.z);
    __nv_bfloat16 h3 = __float2bfloat16(v.w);
    __nv_bfloat16 l0 = __float2bfloat16(v.x - __bfloat162float(h0));
    __nv_bfloat16 l1 = __float2bfloat16(v.y - __bfloat162float(h1));
    __nv_bfloat16 l2 = __float2bfloat16(v.z - __bfloat162float(h2));
    __nv_bfloat16 l3 = __float2bfloat16(v.w - __bfloat162float(h3));
    hi.x = pack_bf16(h0, h1); hi.y = pack_bf16(h2, h3);
    lo.x = pack_bf16(l0, l1); lo.y = pack_bf16(l2, l3);
}

__device__ __forceinline__ void mma_bf16(float* c, const uint32_t* a,
                                         uint32_t b0, uint32_t b1) {
    asm volatile(
        "mma.sync.aligned.m16n8k16.row.col.f32.bf16.bf16.f32 "
        "{%0,%1,%2,%3}, {%4,%5,%6,%7}, {%8,%9}, {%0,%1,%2,%3};"
        : "+f"(c[0]), "+f"(c[1]), "+f"(c[2]), "+f"(c[3])
        : "r"(a[0]), "r"(a[1]), "r"(a[2]), "r"(a[3]),
          "r"(b0), "r"(b1));
}

// ---------------------------------------------------------------------------
// 3xBF16 tensor-core GEMM NT:  C[M,N] (+)= A[M,K] * B[N,K]^T  (fp32-accurate)
// 128x128 CTA tile, 8 warps (4m x 2n), warp tile 32x64, K staged 16,
// double-buffered static smem holding hi/lo bf16x2 planes (row stride 12
// words -> conflict-free fragment LDS). Per product: lo*hi + hi*lo + hi*hi.
// All call sites: M%128==0, N%128==0, K%16==0.
// ---------------------------------------------------------------------------
#define PW_ 12   // plane row stride in 32-bit (bf16x2) words

template<bool ACC>
__global__ __launch_bounds__(256, 2)
void tgemm_nt(const float* __restrict__ A, const float* __restrict__ B,
              float* __restrict__ C, int M, int N, int K) {
    // [buf][hi(0)/lo(1)][128 rows * PW_ words]  -> 48KB total
    __shared__ uint32_t sA[2][2][128 * PW_];
    __shared__ uint32_t sB[2][2][128 * PW_];

    int tid  = threadIdx.x;
    int m0   = blockIdx.y * 128;
    int n0   = blockIdx.x * 128;
    int wid  = tid >> 5;
    int lane = tid & 31;
    int wm = (wid >> 1) * 32;   // 4 warps along m
    int wn = (wid & 1) * 64;    // 2 warps along n
    int lr = lane >> 2;         // 0..7
    int lc = lane & 3;          // 0..3

    // staging: each thread loads 2 float4 per operand tile (128 rows x 16 k)
    int srow  = tid >> 2;         // 0..63
    int scol4 = (tid & 3);        // float4 index along k
    const float* Ag = A + (size_t)(m0 + srow) * K + scol4 * 4;
    const float* Bg = B + (size_t)(n0 + srow) * K + scol4 * 4;
    size_t rstep = (size_t)64 * K;

    int o0 = srow * PW_ + scol4 * 2;          // word offset, 8B aligned
    int o1 = (srow + 64) * PW_ + scol4 * 2;

    float4 av0 = *(const float4*)(Ag);
    float4 av1 = *(const float4*)(Ag + rstep);
    float4 bv0 = *(const float4*)(Bg);
    float4 bv1 = *(const float4*)(Bg + rstep);

    float acc[2][8][4];
    #pragma unroll
    for (int i = 0; i < 2; i++)
        #pragma unroll
        for (int j = 0; j < 8; j++)
            #pragma unroll
            for (int t = 0; t < 4; t++) acc[i][j][t] = 0.f;

    {
        uint2 hi, lo;
        split4(av0, hi, lo);
        *(uint2*)&sA[0][0][o0] = hi; *(uint2*)&sA[0][1][o0] = lo;
        split4(av1, hi, lo);
        *(uint2*)&sA[0][0][o1] = hi; *(uint2*)&sA[0][1][o1] = lo;
        split4(bv0, hi, lo);
        *(uint2*)&sB[0][0][o0] = hi; *(uint2*)&sB[0][1][o0] = lo;
        split4(bv1, hi, lo);
        *(uint2*)&sB[0][0][o1] = hi; *(uint2*)&sB[0][1][o1] = lo;
    }

    int buf = 0;
    for (int k0 = 0; k0 < K; k0 += 16) {
        __syncthreads();
        bool more = (k0 + 16) < K;
        if (more) {
            av0 = *(const float4*)(Ag + k0 + 16);
            av1 = *(const float4*)(Ag + rstep + k0 + 16);
            bv0 = *(const float4*)(Bg + k0 + 16);
            bv1 = *(const float4*)(Bg + rstep + k0 + 16);
        }

        // A fragments (hi & lo) for both m-frags
        uint32_t ah[2][4], al[2][4];
        #pragma unroll
        for (int mf = 0; mf < 2; mf++) {
            int rb = (wm + mf * 16 + lr) * PW_ + lc;
            ah[mf][0] = sA[buf][0][rb];
            ah[mf][1] = sA[buf][0][rb + 8 * PW_];
            ah[mf][2] = sA[buf][0][rb + 4];
            ah[mf][3] = sA[buf][0][rb + 8 * PW_ + 4];
            al[mf][0] = sA[buf][1][rb];
            al[mf][1] = sA[buf][1][rb + 8 * PW_];
            al[mf][2] = sA[buf][1][rb + 4];
            al[mf][3] = sA[buf][1][rb + 8 * PW_ + 4];
        }

        #pragma unroll
        for (int nf = 0; nf < 8; nf++) {
            int cb = (wn + nf * 8 + lr) * PW_ + lc;
            uint32_t bh0 = sB[buf][0][cb], bh1 = sB[buf][0][cb + 4];
            uint32_t bl0 = sB[buf][1][cb], bl1 = sB[buf][1][cb + 4];
            #pragma unroll
            for (int mf = 0; mf < 2; mf++) {
                mma_bf16(acc[mf][nf], al[mf], bh0, bh1);
                mma_bf16(acc[mf][nf], ah[mf], bl0, bl1);
                mma_bf16(acc[mf][nf], ah[mf], bh0, bh1);
            }
        }

        if (more) {
            int nb = buf ^ 1;
            uint2 hi, lo;
            split4(av0, hi, lo);
            *(uint2*)&sA[nb][0][o0] = hi; *(uint2*)&sA[nb][1][o0] = lo;
            split4(av1, hi, lo);
            *(uint2*)&sA[nb][0][o1] = hi; *(uint2*)&sA[nb][1][o1] = lo;
            split4(bv0, hi, lo);
            *(uint2*)&sB[nb][0][o0] = hi; *(uint2*)&sB[nb][1][o0] = lo;
            split4(bv1, hi, lo);
            *(uint2*)&sB[nb][0][o1] = hi; *(uint2*)&sB[nb][1][o1] = lo;
            buf = nb;
        }
    }

    // epilogue
    #pragma unroll
    for (int mf = 0; mf < 2; mf++) {
        #pragma unroll
        for (int nf = 0; nf < 8; nf++) {
            int row = m0 + wm + mf * 16 + lr;
            int col = n0 + wn + nf * 8 + 2 * lc;
            float* p0 = C + (size_t)row * N + col;
            float* p1 = p0 + (size_t)8 * N;
            if (ACC) {
                float2 q0 = *(float2*)p0;
                float2 q1 = *(float2*)p1;
                q0.x += acc[mf][nf][0]; q0.y += acc[mf][nf][1];
                q1.x += acc[mf][nf][2]; q1.y += acc[mf][nf][3];
                *(float2*)p0 = q0;
                *(float2*)p1 = q1;
            } else {
                *(float2*)p0 = make_float2(acc[mf][nf][0], acc[mf][nf][1]);
                *(float2*)p1 = make_float2(acc[mf][nf][2], acc[mf][nf][3]);
            }
        }
    }
}

// ---------------------------------------------------------------------------
// RoPE applied in-place to q and k
// ---------------------------------------------------------------------------
__global__ void rope_kernel(float* __restrict__ q, float* __restrict__ k) {
    int idx = blockIdx.x * blockDim.x + threadIdx.x;
    int t = idx >> 9;
    int p = idx & 511;
    int i = p & 31;
    int s = t & (S_ - 1);
    float inv = expf(-(float)(2 * i) * (1.0f / HD_) * 9.210340371976184f);
    float ang = (float)s * inv;
    float sn, cs;
    sincosf(ang, &sn, &cs);
    size_t off = (size_t)t * DIM_ + p * 2;
    float x0 = q[off], x1 = q[off + 1];
    q[off]     = x0 * cs - x1 * sn;
    q[off + 1] = x0 * sn + x1 * cs;
    x0 = k[off]; x1 = k[off + 1];
    k[off]     = x0 * cs - x1 * sn;
    k[off + 1] = x0 * sn + x1 * cs;
}

// ---------------------------------------------------------------------------
// Flash-style causal attention (fp32)
// ---------------------------------------------------------------------------
__global__ __launch_bounds__(256)
void attn_kernel(const float* __restrict__ q, const float* __restrict__ k,
                 const float* __restrict__ v, float* __restrict__ o) {
    __shared__ float Qs[32][68];
    __shared__ float Ks[64][68];
    __shared__ float Vs[64][68];

    int q0 = blockIdx.x * 32;
    int h  = blockIdx.y;
    int b  = blockIdx.z;
    int tid = threadIdx.x;
    const float scale = 0.125f;

    size_t base = ((size_t)b * S_) * DIM_ + (size_t)h * HD_;

    for (int idx = tid; idx < 32 * 64; idx += 256) {
        int r = idx >> 6, d = idx & 63;
        Qs[r][d] = q[base + (size_t)(q0 + r) * DIM_ + d] * scale;
    }

    int r  = tid >> 3;
    int c8 = tid & 7;

    float m = -INFINITY, l = 0.f;
    float acc[8];
    #pragma unroll
    for (int j = 0; j < 8; j++) acc[j] = 0.f;

    int nkt = (q0 + 31) / 64 + 1;
    for (int kt = 0; kt < nkt; kt++) {
        int k0 = kt * 64;
        __syncthreads();
        for (int idx = tid; idx < 64 * 64; idx += 256) {
            int rr = idx >> 6, d = idx & 63;
            size_t g = base + (size_t)(k0 + rr) * DIM_ + d;
            Ks[rr][d] = k[g];
            Vs[rr][d] = v[g];
        }
        __syncthreads();

        float s[8];
        #pragma unroll
        for (int j = 0; j < 8; j++) s[j] = 0.f;
        #pragma unroll 8
        for (int d = 0; d < 64; d++) {
            float qd = Qs[r][d];
            #pragma unroll
            for (int j = 0; j < 8; j++) s[j] += qd * Ks[c8 + 8 * j][d];
        }

        float tm = -INFINITY;
        #pragma unroll
        for (int j = 0; j < 8; j++) {
            if (k0 + c8 + 8 * j > q0 + r) s[j] = -INFINITY;
            tm = fmaxf(tm, s[j]);
        }
        #pragma unroll
        for (int off = 1; off < 8; off <<= 1)
            tm = fmaxf(tm, __shfl_xor_sync(0xffffffffu, tm, off));

        float mn = fmaxf(m, tm);
        float corr = __expf(m - mn);
        float p[8];
        float ls = 0.f;
        #pragma unroll
        for (int j = 0; j < 8; j++) { p[j] = __expf(s[j] - mn); ls += p[j]; }
        #pragma unroll
        for (int off = 1; off < 8; off <<= 1)
            ls += __shfl_xor_sync(0xffffffffu, ls, off);

        l = l * corr + ls;
        m = mn;
        #pragma unroll
        for (int j = 0; j < 8; j++) acc[j] *= corr;

        #pragma unroll 8
        for (int kk = 0; kk < 64; kk++) {
            float pk = __shfl_sync(0xffffffffu, p[kk >> 3], kk & 7, 8);
            #pragma unroll
            for (int j = 0; j < 8; j++) acc[j] += pk * Vs[kk][c8 + 8 * j];
        }
    }

    float invl = 1.f / l;
    size_t obase = base + (size_t)(q0 + r) * DIM_;
    #pragma unroll
    for (int j = 0; j < 8; j++) o[obase + c8 + 8 * j] = acc[j] * invl;
}

// ---------------------------------------------------------------------------
// SwiGLU elementwise
// ---------------------------------------------------------------------------
__global__ void silu_mul_kernel(float* __restrict__ g1, const float* __restrict__ g3) {
    int idx = blockIdx.x * blockDim.x + threadIdx.x;
    float a = g1[idx];
    float b = g3[idx];
    g1[idx] = a / (1.f + __expf(-a)) * b;
}

// ---------------------------------------------------------------------------
// Host orchestration
// ---------------------------------------------------------------------------
extern "C" void kernel_launch(void* const* d_in, const int* in_sizes, int n_in,
                              void* d_out, int out_size) {
    const int*   tokens      = (const int*)  d_in[0];
    const float* tok_emb     = (const float*)d_in[1];
    const float* wq          = (const float*)d_in[2];
    const float* wk          = (const float*)d_in[3];
    const float* wv          = (const float*)d_in[4];
    const float* wo          = (const float*)d_in[5];
    const float* w1          = (const float*)d_in[6];
    const float* w2          = (const float*)d_in[7];
    const float* w3          = (const float*)d_in[8];
    const float* attn_norm_w = (const float*)d_in[9];
    const float* ffn_norm_w  = (const float*)d_in[10];
    const float* norm_w      = (const float*)d_in[11];
    const float* out_w       = (const float*)d_in[12];

    float *h, *xn, *q, *k, *v, *o, *g1, *g3;
    cudaGetSymbolAddress((void**)&h,  g_h);
    cudaGetSymbolAddress((void**)&xn, g_xn);
    cudaGetSymbolAddress((void**)&q,  g_q);
    cudaGetSymbolAddress((void**)&k,  g_k);
    cudaGetSymbolAddress((void**)&v,  g_v);
    cudaGetSymbolAddress((void**)&o,  g_o);
    cudaGetSymbolAddress((void**)&g1, g_g1);
    cudaGetSymbolAddress((void**)&g3, g_g3);

    embed_kernel<<<T_, 256>>>(tokens, tok_emb, h);

    dim3 gDD (DIM_   / 128, T_ / 128);
    dim3 gDF (HFF_   / 128, T_ / 128);
    dim3 gDV (VOCAB_ / 128, T_ / 128);

    for (int l = 0; l < NL_; l++) {
        const float* wq_l = wq + (size_t)l * DIM_ * DIM_;
        const float* wk_l = wk + (size_t)l * DIM_ * DIM_;
        const float* wv_l = wv + (size_t)l * DIM_ * DIM_;
        const float* wo_l = wo + (size_t)l * DIM_ * DIM_;
        const float* w1_l = w1 + (size_t)l * HFF_ * DIM_;
        const float* w2_l = w2 + (size_t)l * DIM_ * HFF_;
        const float* w3_l = w3 + (size_t)l * HFF_ * DIM_;

        rmsnorm_kernel<<<T_, 256>>>(h, attn_norm_w + (size_t)l * DIM_, xn);
        tgemm_nt<false><<<gDD, 256>>>(xn, wq_l, q, T_, DIM_, DIM_);
        tgemm_nt<false><<<gDD, 256>>>(xn, wk_l, k, T_, DIM_, DIM_);
        tgemm_nt<false><<<gDD, 256>>>(xn, wv_l, v, T_, DIM_, DIM_);
        rope_kernel<<<(T_ * 512) / 256, 256>>>(q, k);
        attn_kernel<<<dim3(S_ / 32, NH_, B_), 256>>>(q, k, v, o);
        tgemm_nt<true ><<<gDD, 256>>>(o, wo_l, h, T_, DIM_, DIM_);

        rmsnorm_kernel<<<T_, 256>>>(h, ffn_norm_w + (size_t)l * DIM_, xn);
        tgemm_nt<false><<<gDF, 256>>>(xn, w1_l, g1, T_, HFF_, DIM_);
        tgemm_nt<false><<<gDF, 256>>>(xn, w3_l, g3, T_, HFF_, DIM_);
        silu_mul_kernel<<<(T_ * HFF_) / 256, 256>>>(g1, g3);
        tgemm_nt<true ><<<gDD, 256>>>(g1, w2_l, h, T_, DIM_, HFF_);
    }

    rmsnorm_kernel<<<T_, 256>>>(h, norm_w, xn);
    tgemm_nt<false><<<gDV, 256>>>(xn, out_w, (float*)d_out, T_, VOCAB_, DIM_);
}

// round 5
// speedup vs baseline: 1.9257x; 1.0363x over previous
#include <cuda_runtime.h>
#include <cuda_bf16.h>
#include <math.h>
#include <stdint.h>

// ---------------------------------------------------------------------------
// Model constants
// ---------------------------------------------------------------------------
#define B_      2
#define S_      2048
#define T_      (B_ * S_)        // 4096 tokens
#define DIM_    1024
#define NH_     16
#define HD_     64
#define NL_     4
#define HFF_    2816
#define VOCAB_  32000

// ---------------------------------------------------------------------------
// Scratch (static device globals: allocation-free per harness rules)
// ---------------------------------------------------------------------------
__device__ float g_h [T_ * DIM_];
__device__ float g_xn[T_ * DIM_];
__device__ float g_q [T_ * DIM_];
__device__ float g_k [T_ * DIM_];
__device__ float g_v [T_ * DIM_];
__device__ float g_o [T_ * DIM_];
__device__ float g_g1[T_ * HFF_];
__device__ float g_g3[T_ * HFF_];

// ---------------------------------------------------------------------------
// Embedding gather
// ---------------------------------------------------------------------------
__global__ void embed_kernel(const int* __restrict__ tokens,
                             const float* __restrict__ emb,
                             float* __restrict__ h) {
    int t = blockIdx.x;
    int tok = tokens[t];
    const float* src = emb + (size_t)tok * DIM_;
    float* dst = h + (size_t)t * DIM_;
    for (int i = threadIdx.x; i < DIM_; i += blockDim.x) dst[i] = src[i];
}

// ---------------------------------------------------------------------------
// RMSNorm
// ---------------------------------------------------------------------------
__global__ void rmsnorm_kernel(const float* __restrict__ x,
                               const float* __restrict__ w,
                               float* __restrict__ y) {
    int t = blockIdx.x;
    const float* xr = x + (size_t)t * DIM_;
    float* yr = y + (size_t)t * DIM_;
    float ss = 0.f;
    #pragma unroll
    for (int i = threadIdx.x; i < DIM_; i += 256) { float v = xr[i]; ss += v * v; }
    #pragma unroll
    for (int off = 16; off > 0; off >>= 1)
        ss += __shfl_xor_sync(0xffffffffu, ss, off);
    __shared__ float red[8];
    if ((threadIdx.x & 31) == 0) red[threadIdx.x >> 5] = ss;
    __syncthreads();
    float tot = 0.f;
    #pragma unroll
    for (int i = 0; i < 8; i++) tot += red[i];
    float sc = rsqrtf(tot * (1.0f / DIM_) + 1e-5f);
    #pragma unroll
    for (int i = threadIdx.x; i < DIM_; i += 256) yr[i] = xr[i] * sc * w[i];
}

// ---------------------------------------------------------------------------
// bf16 split helpers: x ~= hi + lo with ~17 mantissa bits total
// ---------------------------------------------------------------------------
__device__ __forceinline__ uint32_t pack_bf16(__nv_bfloat16 a, __nv_bfloat16 b) {
    return (uint32_t)__bfloat16_as_ushort(a) |
           ((uint32_t)__bfloat16_as_ushort(b) << 16);
}

__device__ __forceinline__ void split4(float4 v, uint2& hi, uint2& lo) {
    __nv_bfloat16 h0 = __float2bfloat16(v.x);
    __nv_bfloat16 h1 = __float2bfloat16(v.y);
    __nv_bfloat16 h2 = __float2bfloat16(v.z);
    __nv_bfloat16 h3 = __float2bfloat16(v.w);
    __nv_bfloat16 l0 = __float2bfloat16(v.x - __bfloat162float(h0));
    __nv_bfloat16 l1 = __float2bfloat16(v.y - __bfloat162float(h1));
    __nv_bfloat16 l2 = __float2bfloat16(v.z - __bfloat162float(h2));
    __nv_bfloat16 l3 = __float2bfloat16(v.w - __bfloat162float(h3));
    hi.x = pack_bf16(h0, h1); hi.y = pack_bf16(h2, h3);
    lo.x = pack_bf16(l0, l1); lo.y = pack_bf16(l2, l3);
}

__device__ __forceinline__ void mma_bf16(float* c, const uint32_t* a,
                                         uint32_t b0, uint32_t b1) {
    asm volatile(
        "mma.sync.aligned.m16n8k16.row.col.f32.bf16.bf16.f32 "
        "{%0,%1,%2,%3}, {%4,%5,%6,%7}, {%8,%9}, {%0,%1,%2,%3};"
        : "+f"(c[0]), "+f"(c[1]), "+f"(c[2]), "+f"(c[3])
        : "r"(a[0]), "r"(a[1]), "r"(a[2]), "r"(a[3]),
          "r"(b0), "r"(b1));
}

__device__ __forceinline__ void ldsm4(uint32_t& r0, uint32_t& r1,
                                      uint32_t& r2, uint32_t& r3, uint32_t addr) {
    asm volatile("ldmatrix.sync.aligned.m8n8.x4.shared.b16 {%0,%1,%2,%3}, [%4];"
        : "=r"(r0), "=r"(r1), "=r"(r2), "=r"(r3) : "r"(addr));
}

// ---------------------------------------------------------------------------
// 3xBF16 tensor-core GEMM NT:  C[M,N] (+)= A[M,K] * B[N,K]^T  (fp32-accurate)
// 128x128 CTA tile, 8 warps (4m x 2n), warp tile 32x64, K staged 16,
// double-buffered smem hi/lo bf16 planes (row stride 12 words; 12i mod 32
// spans 8 distinct bank phases -> conflict-free ldmatrix).
// Fragments loaded with ldmatrix.x4 (12 per warp-stage vs 48 scalar LDS).
// Per product: lo*hi + hi*lo + hi*hi.
// All call sites: M%128==0, N%128==0, K%16==0.
// ---------------------------------------------------------------------------
#define PW_ 12                      // plane row stride in 32-bit words
#define PLB_ (128 * PW_ * 4)        // plane size in bytes

template<bool ACC>
__global__ __launch_bounds__(256, 2)
void tgemm_nt(const float* __restrict__ A, const float* __restrict__ B,
              float* __restrict__ C, int M, int N, int K) {
    // [buf][hi(0)/lo(1)][128 rows * PW_ words]  -> 48KB total
    __shared__ __align__(16) uint32_t sA[2][2][128 * PW_];
    __shared__ __align__(16) uint32_t sB[2][2][128 * PW_];

    int tid  = threadIdx.x;
    int m0   = blockIdx.y * 128;
    int n0   = blockIdx.x * 128;
    int wid  = tid >> 5;
    int lane = tid & 31;
    int wm = (wid >> 1) * 32;   // 4 warps along m
    int wn = (wid & 1) * 64;    // 2 warps along n
    int lr = lane >> 2;         // 0..7
    int lc = lane & 3;          // 0..3

    uint32_t sAbase = (uint32_t)__cvta_generic_to_shared(&sA[0][0][0]);
    uint32_t sBbase = (uint32_t)__cvta_generic_to_shared(&sB[0][0][0]);

    // ldmatrix per-lane byte offsets within a plane
    // A (per m-frag): tiles {m0-7/k0-7, m8-15/k0-7, m0-7/k8-15, m8-15/k8-15}
    uint32_t aoff[2];
    #pragma unroll
    for (int mf = 0; mf < 2; mf++) {
        int row = wm + mf * 16 + (lane & 7) + ((lane >> 3) & 1) * 8;
        aoff[mf] = row * (PW_ * 4) + (lane >> 4) * 16;
    }
    // B (per n-frag pair): tiles {nf0/k0-7, nf0/k8-15, nf1/k0-7, nf1/k8-15}
    uint32_t boff[4];
    #pragma unroll
    for (int nfp = 0; nfp < 4; nfp++) {
        int row = wn + nfp * 16 + (lane & 7) + (lane >> 4) * 8;
        boff[nfp] = row * (PW_ * 4) + ((lane >> 3) & 1) * 16;
    }

    // staging: each thread loads 2 float4 per operand tile (128 rows x 16 k)
    int srow  = tid >> 2;         // 0..63
    int scol4 = (tid & 3);        // float4 index along k
    const float* Ag = A + (size_t)(m0 + srow) * K + scol4 * 4;
    const float* Bg = B + (size_t)(n0 + srow) * K + scol4 * 4;
    size_t rstep = (size_t)64 * K;

    int o0 = srow * PW_ + scol4 * 2;          // word offset, 8B aligned
    int o1 = (srow + 64) * PW_ + scol4 * 2;

    float4 av0 = *(const float4*)(Ag);
    float4 av1 = *(const float4*)(Ag + rstep);
    float4 bv0 = *(const float4*)(Bg);
    float4 bv1 = *(const float4*)(Bg + rstep);

    float acc[2][8][4];
    #pragma unroll
    for (int i = 0; i < 2; i++)
        #pragma unroll
        for (int j = 0; j < 8; j++)
            #pragma unroll
            for (int t = 0; t < 4; t++) acc[i][j][t] = 0.f;

    {
        uint2 hi, lo;
        split4(av0, hi, lo);
        *(uint2*)&sA[0][0][o0] = hi; *(uint2*)&sA[0][1][o0] = lo;
        split4(av1, hi, lo);
        *(uint2*)&sA[0][0][o1] = hi; *(uint2*)&sA[0][1][o1] = lo;
        split4(bv0, hi, lo);
        *(uint2*)&sB[0][0][o0] = hi; *(uint2*)&sB[0][1][o0] = lo;
        split4(bv1, hi, lo);
        *(uint2*)&sB[0][0][o1] = hi; *(uint2*)&sB[0][1][o1] = lo;
    }

    int buf = 0;
    for (int k0 = 0; k0 < K; k0 += 16) {
        __syncthreads();
        bool more = (k0 + 16) < K;
        if (more) {
            av0 = *(const float4*)(Ag + k0 + 16);
            av1 = *(const float4*)(Ag + rstep + k0 + 16);
            bv0 = *(const float4*)(Bg + k0 + 16);
            bv1 = *(const float4*)(Bg + rstep + k0 + 16);
        }

        uint32_t baseA = sAbase + (uint32_t)buf * 2 * PLB_;
        uint32_t baseB = sBbase + (uint32_t)buf * 2 * PLB_;

        // A fragments hi & lo
        uint32_t ah[2][4], al[2][4];
        #pragma unroll
        for (int mf = 0; mf < 2; mf++) {
            ldsm4(ah[mf][0], ah[mf][1], ah[mf][2], ah[mf][3], baseA + aoff[mf]);
            ldsm4(al[mf][0], al[mf][1], al[mf][2], al[mf][3], baseA + PLB_ + aoff[mf]);
        }

        #pragma unroll
        for (int nfp = 0; nfp < 4; nfp++) {
            uint32_t bh[4], bl[4];
            ldsm4(bh[0], bh[1], bh[2], bh[3], baseB + boff[nfp]);
            ldsm4(bl[0], bl[1], bl[2], bl[3], baseB + PLB_ + boff[nfp]);
            int nf0 = nfp * 2, nf1 = nfp * 2 + 1;
            #pragma unroll
            for (int mf = 0; mf < 2; mf++) {
                mma_bf16(acc[mf][nf0], al[mf], bh[0], bh[1]);
                mma_bf16(acc[mf][nf0], ah[mf], bl[0], bl[1]);
                mma_bf16(acc[mf][nf0], ah[mf], bh[0], bh[1]);
                mma_bf16(acc[mf][nf1], al[mf], bh[2], bh[3]);
                mma_bf16(acc[mf][nf1], ah[mf], bl[2], bl[3]);
                mma_bf16(acc[mf][nf1], ah[mf], bh[2], bh[3]);
            }
        }

        if (more) {
            int nb = buf ^ 1;
            uint2 hi, lo;
            split4(av0, hi, lo);
            *(uint2*)&sA[nb][0][o0] = hi; *(uint2*)&sA[nb][1][o0] = lo;
            split4(av1, hi, lo);
            *(uint2*)&sA[nb][0][o1] = hi; *(uint2*)&sA[nb][1][o1] = lo;
            split4(bv0, hi, lo);
            *(uint2*)&sB[nb][0][o0] = hi; *(uint2*)&sB[nb][1][o0] = lo;
            split4(bv1, hi, lo);
            *(uint2*)&sB[nb][0][o1] = hi; *(uint2*)&sB[nb][1][o1] = lo;
            buf = nb;
        }
    }

    // epilogue
    #pragma unroll
    for (int mf = 0; mf < 2; mf++) {
        #pragma unroll
        for (int nf = 0; nf < 8; nf++) {
            int row = m0 + wm + mf * 16 + lr;
            int col = n0 + wn + nf * 8 + 2 * lc;
            float* p0 = C + (size_t)row * N + col;
            float* p1 = p0 + (size_t)8 * N;
            if (ACC) {
                float2 q0 = *(float2*)p0;
                float2 q1 = *(float2*)p1;
                q0.x += acc[mf][nf][0]; q0.y += acc[mf][nf][1];
                q1.x += acc[mf][nf][2]; q1.y += acc[mf][nf][3];
                *(float2*)p0 = q0;
                *(float2*)p1 = q1;
            } else {
                *(float2*)p0 = make_float2(acc[mf][nf][0], acc[mf][nf][1]);
                *(float2*)p1 = make_float2(acc[mf][nf][2], acc[mf][nf][3]);
            }
        }
    }
}

// ---------------------------------------------------------------------------
// RoPE applied in-place to q and k
// ---------------------------------------------------------------------------
__global__ void rope_kernel(float* __restrict__ q, float* __restrict__ k) {
    int idx = blockIdx.x * blockDim.x + threadIdx.x;
    int t = idx >> 9;
    int p = idx & 511;
    int i = p & 31;
    int s = t & (S_ - 1);
    float inv = expf(-(float)(2 * i) * (1.0f / HD_) * 9.210340371976184f);
    float ang = (float)s * inv;
    float sn, cs;
    sincosf(ang, &sn, &cs);
    size_t off = (size_t)t * DIM_ + p * 2;
    float x0 = q[off], x1 = q[off + 1];
    q[off]     = x0 * cs - x1 * sn;
    q[off + 1] = x0 * sn + x1 * cs;
    x0 = k[off]; x1 = k[off + 1];
    k[off]     = x0 * cs - x1 * sn;
    k[off + 1] = x0 * sn + x1 * cs;
}

// ---------------------------------------------------------------------------
// Flash-style causal attention (fp32)
// ---------------------------------------------------------------------------
__global__ __launch_bounds__(256)
void attn_kernel(const float* __restrict__ q, const float* __restrict__ k,
                 const float* __restrict__ v, float* __restrict__ o) {
    __shared__ float Qs[32][68];
    __shared__ float Ks[64][68];
    __shared__ float Vs[64][68];

    int q0 = blockIdx.x * 32;
    int h  = blockIdx.y;
    int b  = blockIdx.z;
    int tid = threadIdx.x;
    const float scale = 0.125f;

    size_t base = ((size_t)b * S_) * DIM_ + (size_t)h * HD_;

    for (int idx = tid; idx < 32 * 64; idx += 256) {
        int r = idx >> 6, d = idx & 63;
        Qs[r][d] = q[base + (size_t)(q0 + r) * DIM_ + d] * scale;
    }

    int r  = tid >> 3;
    int c8 = tid & 7;

    float m = -INFINITY, l = 0.f;
    float acc[8];
    #pragma unroll
    for (int j = 0; j < 8; j++) acc[j] = 0.f;

    int nkt = (q0 + 31) / 64 + 1;
    for (int kt = 0; kt < nkt; kt++) {
        int k0 = kt * 64;
        __syncthreads();
        for (int idx = tid; idx < 64 * 64; idx += 256) {
            int rr = idx >> 6, d = idx & 63;
            size_t g = base + (size_t)(k0 + rr) * DIM_ + d;
            Ks[rr][d] = k[g];
            Vs[rr][d] = v[g];
        }
        __syncthreads();

        float s[8];
        #pragma unroll
        for (int j = 0; j < 8; j++) s[j] = 0.f;
        #pragma unroll 8
        for (int d = 0; d < 64; d++) {
            float qd = Qs[r][d];
            #pragma unroll
            for (int j = 0; j < 8; j++) s[j] += qd * Ks[c8 + 8 * j][d];
        }

        float tm = -INFINITY;
        #pragma unroll
        for (int j = 0; j < 8; j++) {
            if (k0 + c8 + 8 * j > q0 + r) s[j] = -INFINITY;
            tm = fmaxf(tm, s[j]);
        }
        #pragma unroll
        for (int off = 1; off < 8; off <<= 1)
            tm = fmaxf(tm, __shfl_xor_sync(0xffffffffu, tm, off));

        float mn = fmaxf(m, tm);
        float corr = __expf(m - mn);
        float p[8];
        float ls = 0.f;
        #pragma unroll
        for (int j = 0; j < 8; j++) { p[j] = __expf(s[j] - mn); ls += p[j]; }
        #pragma unroll
        for (int off = 1; off < 8; off <<= 1)
            ls += __shfl_xor_sync(0xffffffffu, ls, off);

        l = l * corr + ls;
        m = mn;
        #pragma unroll
        for (int j = 0; j < 8; j++) acc[j] *= corr;

        #pragma unroll 8
        for (int kk = 0; kk < 64; kk++) {
            float pk = __shfl_sync(0xffffffffu, p[kk >> 3], kk & 7, 8);
            #pragma unroll
            for (int j = 0; j < 8; j++) acc[j] += pk * Vs[kk][c8 + 8 * j];
        }
    }

    float invl = 1.f / l;
    size_t obase = base + (size_t)(q0 + r) * DIM_;
    #pragma unroll
    for (int j = 0; j < 8; j++) o[obase + c8 + 8 * j] = acc[j] * invl;
}

// ---------------------------------------------------------------------------
// SwiGLU elementwise
// ---------------------------------------------------------------------------
__global__ void silu_mul_kernel(float* __restrict__ g1, const float* __restrict__ g3) {
    int idx = blockIdx.x * blockDim.x + threadIdx.x;
    float a = g1[idx];
    float b = g3[idx];
    g1[idx] = a / (1.f + __expf(-a)) * b;
}

// ---------------------------------------------------------------------------
// Host orchestration
// ---------------------------------------------------------------------------
extern "C" void kernel_launch(void* const* d_in, const int* in_sizes, int n_in,
                              void* d_out, int out_size) {
    const int*   tokens      = (const int*)  d_in[0];
    const float* tok_emb     = (const float*)d_in[1];
    const float* wq          = (const float*)d_in[2];
    const float* wk          = (const float*)d_in[3];
    const float* wv          = (const float*)d_in[4];
    const float* wo          = (const float*)d_in[5];
    const float* w1          = (const float*)d_in[6];
    const float* w2          = (const float*)d_in[7];
    const float* w3          = (const float*)d_in[8];
    const float* attn_norm_w = (const float*)d_in[9];
    const float* ffn_norm_w  = (const float*)d_in[10];
    const float* norm_w      = (const float*)d_in[11];
    const float* out_w       = (const float*)d_in[12];

    float *h, *xn, *q, *k, *v, *o, *g1, *g3;
    cudaGetSymbolAddress((void**)&h,  g_h);
    cudaGetSymbolAddress((void**)&xn, g_xn);
    cudaGetSymbolAddress((void**)&q,  g_q);
    cudaGetSymbolAddress((void**)&k,  g_k);
    cudaGetSymbolAddress((void**)&v,  g_v);
    cudaGetSymbolAddress((void**)&o,  g_o);
    cudaGetSymbolAddress((void**)&g1, g_g1);
    cudaGetSymbolAddress((void**)&g3, g_g3);

    embed_kernel<<<T_, 256>>>(tokens, tok_emb, h);

    dim3 gDD (DIM_   / 128, T_ / 128);
    dim3 gDF (HFF_   / 128, T_ / 128);
    dim3 gDV (VOCAB_ / 128, T_ / 128);

    for (int l = 0; l < NL_; l++) {
        const float* wq_l = wq + (size_t)l * DIM_ * DIM_;
        const float* wk_l = wk + (size_t)l * DIM_ * DIM_;
        const float* wv_l = wv + (size_t)l * DIM_ * DIM_;
        const float* wo_l = wo + (size_t)l * DIM_ * DIM_;
        const float* w1_l = w1 + (size_t)l * HFF_ * DIM_;
        const float* w2_l = w2 + (size_t)l * DIM_ * HFF_;
        const float* w3_l = w3 + (size_t)l * HFF_ * DIM_;

        rmsnorm_kernel<<<T_, 256>>>(h, attn_norm_w + (size_t)l * DIM_, xn);
        tgemm_nt<false><<<gDD, 256>>>(xn, wq_l, q, T_, DIM_, DIM_);
        tgemm_nt<false><<<gDD, 256>>>(xn, wk_l, k, T_, DIM_, DIM_);
        tgemm_nt<false><<<gDD, 256>>>(xn, wv_l, v, T_, DIM_, DIM_);
        rope_kernel<<<(T_ * 512) / 256, 256>>>(q, k);
        attn_kernel<<<dim3(S_ / 32, NH_, B_), 256>>>(q, k, v, o);
        tgemm_nt<true ><<<gDD, 256>>>(o, wo_l, h, T_, DIM_, DIM_);

        rmsnorm_kernel<<<T_, 256>>>(h, ffn_norm_w + (size_t)l * DIM_, xn);
        tgemm_nt<false><<<gDF, 256>>>(xn, w1_l, g1, T_, HFF_, DIM_);
        tgemm_nt<false><<<gDF, 256>>>(xn, w3_l, g3, T_, HFF_, DIM_);
        silu_mul_kernel<<<(T_ * HFF_) / 256, 256>>>(g1, g3);
        tgemm_nt<true ><<<gDD, 256>>>(g1, w2_l, h, T_, DIM_, HFF_);
    }

    rmsnorm_kernel<<<T_, 256>>>(h, norm_w, xn);
    tgemm_nt<false><<<gDV, 256>>>(xn, out_w, (float*)d_out, T_, VOCAB_, DIM_);
}

// round 6
// speedup vs baseline: 3.0711x; 1.5948x over previous
#include <cuda_runtime.h>
#include <cuda_bf16.h>
#include <math.h>
#include <stdint.h>

// ---------------------------------------------------------------------------
// Model constants
// ---------------------------------------------------------------------------
#define B_      2
#define S_      2048
#define T_      (B_ * S_)        // 4096 tokens
#define DIM_    1024
#define NH_     16
#define HD_     64
#define NL_     4
#define HFF_    2816
#define VOCAB_  32000

// ---------------------------------------------------------------------------
// Scratch (static device globals: allocation-free per harness rules)
// ---------------------------------------------------------------------------
__device__ float g_h [T_ * DIM_];
__device__ float g_xn[T_ * DIM_];
__device__ float g_q [T_ * DIM_];
__device__ float g_k [T_ * DIM_];
__device__ float g_v [T_ * DIM_];
__device__ float g_o [T_ * DIM_];
__device__ float g_g1[T_ * HFF_];
__device__ float g_g3[T_ * HFF_];

// ---------------------------------------------------------------------------
// Embedding gather
// ---------------------------------------------------------------------------
__global__ void embed_kernel(const int* __restrict__ tokens,
                             const float* __restrict__ emb,
                             float* __restrict__ h) {
    int t = blockIdx.x;
    int tok = tokens[t];
    const float* src = emb + (size_t)tok * DIM_;
    float* dst = h + (size_t)t * DIM_;
    for (int i = threadIdx.x; i < DIM_; i += blockDim.x) dst[i] = src[i];
}

// ---------------------------------------------------------------------------
// RMSNorm
// ---------------------------------------------------------------------------
__global__ void rmsnorm_kernel(const float* __restrict__ x,
                               const float* __restrict__ w,
                               float* __restrict__ y) {
    int t = blockIdx.x;
    const float* xr = x + (size_t)t * DIM_;
    float* yr = y + (size_t)t * DIM_;
    float ss = 0.f;
    #pragma unroll
    for (int i = threadIdx.x; i < DIM_; i += 256) { float v = xr[i]; ss += v * v; }
    #pragma unroll
    for (int off = 16; off > 0; off >>= 1)
        ss += __shfl_xor_sync(0xffffffffu, ss, off);
    __shared__ float red[8];
    if ((threadIdx.x & 31) == 0) red[threadIdx.x >> 5] = ss;
    __syncthreads();
    float tot = 0.f;
    #pragma unroll
    for (int i = 0; i < 8; i++) tot += red[i];
    float sc = rsqrtf(tot * (1.0f / DIM_) + 1e-5f);
    #pragma unroll
    for (int i = threadIdx.x; i < DIM_; i += 256) yr[i] = xr[i] * sc * w[i];
}

// ---------------------------------------------------------------------------
// bf16 split helpers
// ---------------------------------------------------------------------------
__device__ __forceinline__ uint32_t pack_bf16(__nv_bfloat16 a, __nv_bfloat16 b) {
    return (uint32_t)__bfloat16_as_ushort(a) |
           ((uint32_t)__bfloat16_as_ushort(b) << 16);
}

__device__ __forceinline__ uint32_t pack2f(float a, float b) {
    return pack_bf16(__float2bfloat16(a), __float2bfloat16(b));
}

__device__ __forceinline__ uint32_t pack2f_lo(float a, float b) {
    float ha = __bfloat162float(__float2bfloat16(a));
    float hb = __bfloat162float(__float2bfloat16(b));
    return pack_bf16(__float2bfloat16(a - ha), __float2bfloat16(b - hb));
}

__device__ __forceinline__ void split4(float4 v, uint2& hi, uint2& lo) {
    __nv_bfloat16 h0 = __float2bfloat16(v.x);
    __nv_bfloat16 h1 = __float2bfloat16(v.y);
    __nv_bfloat16 h2 = __float2bfloat16(v.z);
    __nv_bfloat16 h3 = __float2bfloat16(v.w);
    __nv_bfloat16 l0 = __float2bfloat16(v.x - __bfloat162float(h0));
    __nv_bfloat16 l1 = __float2bfloat16(v.y - __bfloat162float(h1));
    __nv_bfloat16 l2 = __float2bfloat16(v.z - __bfloat162float(h2));
    __nv_bfloat16 l3 = __float2bfloat16(v.w - __bfloat162float(h3));
    hi.x = pack_bf16(h0, h1); hi.y = pack_bf16(h2, h3);
    lo.x = pack_bf16(l0, l1); lo.y = pack_bf16(l2, l3);
}

__device__ __forceinline__ void mma_bf16(float* c, const uint32_t* a,
                                         uint32_t b0, uint32_t b1) {
    asm volatile(
        "mma.sync.aligned.m16n8k16.row.col.f32.bf16.bf16.f32 "
        "{%0,%1,%2,%3}, {%4,%5,%6,%7}, {%8,%9}, {%0,%1,%2,%3};"
        : "+f"(c[0]), "+f"(c[1]), "+f"(c[2]), "+f"(c[3])
        : "r"(a[0]), "r"(a[1]), "r"(a[2]), "r"(a[3]),
          "r"(b0), "r"(b1));
}

__device__ __forceinline__ void ldsm4(uint32_t& r0, uint32_t& r1,
                                      uint32_t& r2, uint32_t& r3, uint32_t addr) {
    asm volatile("ldmatrix.sync.aligned.m8n8.x4.shared.b16 {%0,%1,%2,%3}, [%4];"
        : "=r"(r0), "=r"(r1), "=r"(r2), "=r"(r3) : "r"(addr));
}

__device__ __forceinline__ void ldsm4t(uint32_t& r0, uint32_t& r1,
                                       uint32_t& r2, uint32_t& r3, uint32_t addr) {
    asm volatile("ldmatrix.sync.aligned.m8n8.x4.trans.shared.b16 {%0,%1,%2,%3}, [%4];"
        : "=r"(r0), "=r"(r1), "=r"(r2), "=r"(r3) : "r"(addr));
}

// ---------------------------------------------------------------------------
// 3xBF16 tensor-core GEMM NT (unchanged from R5)
// ---------------------------------------------------------------------------
#define PW_ 12
#define PLB_ (128 * PW_ * 4)

template<bool ACC>
__global__ __launch_bounds__(256, 2)
void tgemm_nt(const float* __restrict__ A, const float* __restrict__ B,
              float* __restrict__ C, int M, int N, int K) {
    __shared__ __align__(16) uint32_t sA[2][2][128 * PW_];
    __shared__ __align__(16) uint32_t sB[2][2][128 * PW_];

    int tid  = threadIdx.x;
    int m0   = blockIdx.y * 128;
    int n0   = blockIdx.x * 128;
    int wid  = tid >> 5;
    int lane = tid & 31;
    int wm = (wid >> 1) * 32;
    int wn = (wid & 1) * 64;
    int lr = lane >> 2;
    int lc = lane & 3;

    uint32_t sAbase = (uint32_t)__cvta_generic_to_shared(&sA[0][0][0]);
    uint32_t sBbase = (uint32_t)__cvta_generic_to_shared(&sB[0][0][0]);

    uint32_t aoff[2];
    #pragma unroll
    for (int mf = 0; mf < 2; mf++) {
        int row = wm + mf * 16 + (lane & 7) + ((lane >> 3) & 1) * 8;
        aoff[mf] = row * (PW_ * 4) + (lane >> 4) * 16;
    }
    uint32_t boff[4];
    #pragma unroll
    for (int nfp = 0; nfp < 4; nfp++) {
        int row = wn + nfp * 16 + (lane & 7) + (lane >> 4) * 8;
        boff[nfp] = row * (PW_ * 4) + ((lane >> 3) & 1) * 16;
    }

    int srow  = tid >> 2;
    int scol4 = (tid & 3);
    const float* Ag = A + (size_t)(m0 + srow) * K + scol4 * 4;
    const float* Bg = B + (size_t)(n0 + srow) * K + scol4 * 4;
    size_t rstep = (size_t)64 * K;

    int o0 = srow * PW_ + scol4 * 2;
    int o1 = (srow + 64) * PW_ + scol4 * 2;

    float4 av0 = *(const float4*)(Ag);
    float4 av1 = *(const float4*)(Ag + rstep);
    float4 bv0 = *(const float4*)(Bg);
    float4 bv1 = *(const float4*)(Bg + rstep);

    float acc[2][8][4];
    #pragma unroll
    for (int i = 0; i < 2; i++)
        #pragma unroll
        for (int j = 0; j < 8; j++)
            #pragma unroll
            for (int t = 0; t < 4; t++) acc[i][j][t] = 0.f;

    {
        uint2 hi, lo;
        split4(av0, hi, lo);
        *(uint2*)&sA[0][0][o0] = hi; *(uint2*)&sA[0][1][o0] = lo;
        split4(av1, hi, lo);
        *(uint2*)&sA[0][0][o1] = hi; *(uint2*)&sA[0][1][o1] = lo;
        split4(bv0, hi, lo);
        *(uint2*)&sB[0][0][o0] = hi; *(uint2*)&sB[0][1][o0] = lo;
        split4(bv1, hi, lo);
        *(uint2*)&sB[0][0][o1] = hi; *(uint2*)&sB[0][1][o1] = lo;
    }

    int buf = 0;
    for (int k0 = 0; k0 < K; k0 += 16) {
        __syncthreads();
        bool more = (k0 + 16) < K;
        if (more) {
            av0 = *(const float4*)(Ag + k0 + 16);
            av1 = *(const float4*)(Ag + rstep + k0 + 16);
            bv0 = *(const float4*)(Bg + k0 + 16);
            bv1 = *(const float4*)(Bg + rstep + k0 + 16);
        }

        uint32_t baseA = sAbase + (uint32_t)buf * 2 * PLB_;
        uint32_t baseB = sBbase + (uint32_t)buf * 2 * PLB_;

        uint32_t ah[2][4], al[2][4];
        #pragma unroll
        for (int mf = 0; mf < 2; mf++) {
            ldsm4(ah[mf][0], ah[mf][1], ah[mf][2], ah[mf][3], baseA + aoff[mf]);
            ldsm4(al[mf][0], al[mf][1], al[mf][2], al[mf][3], baseA + PLB_ + aoff[mf]);
        }

        #pragma unroll
        for (int nfp = 0; nfp < 4; nfp++) {
            uint32_t bh[4], bl[4];
            ldsm4(bh[0], bh[1], bh[2], bh[3], baseB + boff[nfp]);
            ldsm4(bl[0], bl[1], bl[2], bl[3], baseB + PLB_ + boff[nfp]);
            int nf0 = nfp * 2, nf1 = nfp * 2 + 1;
            #pragma unroll
            for (int mf = 0; mf < 2; mf++) {
                mma_bf16(acc[mf][nf0], al[mf], bh[0], bh[1]);
                mma_bf16(acc[mf][nf0], ah[mf], bl[0], bl[1]);
                mma_bf16(acc[mf][nf0], ah[mf], bh[0], bh[1]);
                mma_bf16(acc[mf][nf1], al[mf], bh[2], bh[3]);
                mma_bf16(acc[mf][nf1], ah[mf], bl[2], bl[3]);
                mma_bf16(acc[mf][nf1], ah[mf], bh[2], bh[3]);
            }
        }

        if (more) {
            int nb = buf ^ 1;
            uint2 hi, lo;
            split4(av0, hi, lo);
            *(uint2*)&sA[nb][0][o0] = hi; *(uint2*)&sA[nb][1][o0] = lo;
            split4(av1, hi, lo);
            *(uint2*)&sA[nb][0][o1] = hi; *(uint2*)&sA[nb][1][o1] = lo;
            split4(bv0, hi, lo);
            *(uint2*)&sB[nb][0][o0] = hi; *(uint2*)&sB[nb][1][o0] = lo;
            split4(bv1, hi, lo);
            *(uint2*)&sB[nb][0][o1] = hi; *(uint2*)&sB[nb][1][o1] = lo;
            buf = nb;
        }
    }

    #pragma unroll
    for (int mf = 0; mf < 2; mf++) {
        #pragma unroll
        for (int nf = 0; nf < 8; nf++) {
            int row = m0 + wm + mf * 16 + lr;
            int col = n0 + wn + nf * 8 + 2 * lc;
            float* p0 = C + (size_t)row * N + col;
            float* p1 = p0 + (size_t)8 * N;
            if (ACC) {
                float2 q0 = *(float2*)p0;
                float2 q1 = *(float2*)p1;
                q0.x += acc[mf][nf][0]; q0.y += acc[mf][nf][1];
                q1.x += acc[mf][nf][2]; q1.y += acc[mf][nf][3];
                *(float2*)p0 = q0;
                *(float2*)p1 = q1;
            } else {
                *(float2*)p0 = make_float2(acc[mf][nf][0], acc[mf][nf][1]);
                *(float2*)p1 = make_float2(acc[mf][nf][2], acc[mf][nf][3]);
            }
        }
    }
}

// ---------------------------------------------------------------------------
// RoPE applied in-place to q and k
// ---------------------------------------------------------------------------
__global__ void rope_kernel(float* __restrict__ q, float* __restrict__ k) {
    int idx = blockIdx.x * blockDim.x + threadIdx.x;
    int t = idx >> 9;
    int p = idx & 511;
    int i = p & 31;
    int s = t & (S_ - 1);
    float inv = expf(-(float)(2 * i) * (1.0f / HD_) * 9.210340371976184f);
    float ang = (float)s * inv;
    float sn, cs;
    sincosf(ang, &sn, &cs);
    size_t off = (size_t)t * DIM_ + p * 2;
    float x0 = q[off], x1 = q[off + 1];
    q[off]     = x0 * cs - x1 * sn;
    q[off + 1] = x0 * sn + x1 * cs;
    x0 = k[off]; x1 = k[off + 1];
    k[off]     = x0 * cs - x1 * sn;
    k[off + 1] = x0 * sn + x1 * cs;
}

// ---------------------------------------------------------------------------
// Tensor-core flash attention (bf16 split, fp32 softmax).
// Grid (S/64, NH, B), 128 threads (4 warps x 16 query rows).
// K/V streamed in 64-key tiles; scores 3-term bf16 mma; P kept in registers
// (score fragments ARE the PV A-fragments); V via ldmatrix.trans.
// ---------------------------------------------------------------------------
#define APW_ 36                  // words per smem row (64 bf16 + pad)
#define APLB_ (64 * APW_ * 4)    // plane bytes

__global__ __launch_bounds__(128)
void attn_mma_kernel(const float* __restrict__ q, const float* __restrict__ k,
                     const float* __restrict__ v, float* __restrict__ o) {
    __shared__ __align__(16) uint32_t sK[2][64 * APW_];
    __shared__ __align__(16) uint32_t sV[2][64 * APW_];

    int q0  = blockIdx.x * 64;
    int h   = blockIdx.y;
    int b   = blockIdx.z;
    int tid = threadIdx.x;
    int w   = tid >> 5;
    int lane = tid & 31;
    int lr = lane >> 2, lc = lane & 3;

    size_t base = ((size_t)b * S_) * DIM_ + (size_t)h * HD_;

    uint32_t sKb = (uint32_t)__cvta_generic_to_shared(&sK[0][0]);
    uint32_t sVb = (uint32_t)__cvta_generic_to_shared(&sV[0][0]);

    // ---- stage Q (scaled) into sK, extract A-fragments ----
    #pragma unroll
    for (int i = 0; i < 8; i++) {
        int idx = tid + i * 128;           // 64 rows x 16 float4
        int row = idx >> 4, c4 = idx & 15;
        float4 qv = *(const float4*)(q + base + (size_t)(q0 + row) * DIM_ + c4 * 4);
        qv.x *= 0.125f; qv.y *= 0.125f; qv.z *= 0.125f; qv.w *= 0.125f;
        uint2 hi, lo;
        split4(qv, hi, lo);
        int wo = row * APW_ + c4 * 2;
        *(uint2*)&sK[0][wo] = hi;
        *(uint2*)&sK[1][wo] = lo;
    }
    __syncthreads();

    uint32_t Qh[4][4], Ql[4][4];
    {
        int arow = w * 16 + (lane & 7) + ((lane >> 3) & 1) * 8;
        uint32_t ab = arow * (APW_ * 4) + (lane >> 4) * 16;
        #pragma unroll
        for (int kc = 0; kc < 4; kc++) {
            ldsm4(Qh[kc][0], Qh[kc][1], Qh[kc][2], Qh[kc][3], sKb + ab + kc * 32);
            ldsm4(Ql[kc][0], Ql[kc][1], Ql[kc][2], Ql[kc][3], sKb + APLB_ + ab + kc * 32);
        }
    }

    // fragment offsets for K (non-trans) and V (trans)
    uint32_t koff[4], voff[4][4];
    #pragma unroll
    for (int nfp = 0; nfp < 4; nfp++) {
        int row = nfp * 16 + (lane & 7) + (lane >> 4) * 8;
        koff[nfp] = row * (APW_ * 4) + ((lane >> 3) & 1) * 16;
        #pragma unroll
        for (int kc = 0; kc < 4; kc++) {
            int vrow = kc * 16 + ((lane >> 3) & 1) * 8 + (lane & 7);
            voff[nfp][kc] = vrow * (APW_ * 4) + (nfp * 2 + (lane >> 4)) * 16;
        }
    }

    float accO[8][4];
    #pragma unroll
    for (int nf = 0; nf < 8; nf++)
        #pragma unroll
        for (int t = 0; t < 4; t++) accO[nf][t] = 0.f;
    float m0 = -INFINITY, m1 = -INFINITY, l0 = 0.f, l1 = 0.f;

    int nkt = blockIdx.x + 1;
    for (int kt = 0; kt < nkt; kt++) {
        int k0 = kt * 64;
        __syncthreads();
        // load K and V tiles (64 keys x 64 d fp32), split into bf16 hi/lo
        #pragma unroll
        for (int i = 0; i < 8; i++) {
            int idx = tid + i * 128;
            int row = idx >> 4, c4 = idx & 15;
            size_t g = base + (size_t)(k0 + row) * DIM_ + c4 * 4;
            int wo = row * APW_ + c4 * 2;
            uint2 hi, lo;
            split4(*(const float4*)(k + g), hi, lo);
            *(uint2*)&sK[0][wo] = hi; *(uint2*)&sK[1][wo] = lo;
            split4(*(const float4*)(v + g), hi, lo);
            *(uint2*)&sV[0][wo] = hi; *(uint2*)&sV[1][wo] = lo;
        }
        __syncthreads();

        // ---- scores: S = Q K^T (3-term bf16 split) ----
        float sc[8][4];
        #pragma unroll
        for (int nf = 0; nf < 8; nf++)
            #pragma unroll
            for (int t = 0; t < 4; t++) sc[nf][t] = 0.f;

        #pragma unroll
        for (int nfp = 0; nfp < 4; nfp++) {
            #pragma unroll
            for (int kc = 0; kc < 4; kc++) {
                uint32_t bh[4], bl[4];
                ldsm4(bh[0], bh[1], bh[2], bh[3], sKb + koff[nfp] + kc * 32);
                ldsm4(bl[0], bl[1], bl[2], bl[3], sKb + APLB_ + koff[nfp] + kc * 32);
                int nf0 = nfp * 2, nf1 = nf0 + 1;
                mma_bf16(sc[nf0], Ql[kc], bh[0], bh[1]);
                mma_bf16(sc[nf0], Qh[kc], bl[0], bl[1]);
                mma_bf16(sc[nf0], Qh[kc], bh[0], bh[1]);
                mma_bf16(sc[nf1], Ql[kc], bh[2], bh[3]);
                mma_bf16(sc[nf1], Qh[kc], bl[2], bl[3]);
                mma_bf16(sc[nf1], Qh[kc], bh[2], bh[3]);
            }
        }

        // ---- causal mask on the diagonal tile ----
        if (kt == nkt - 1) {
            int row0 = w * 16 + lr;          // relative (k0 == q0 here)
            int row1 = row0 + 8;
            #pragma unroll
            for (int nf = 0; nf < 8; nf++) {
                int col = nf * 8 + 2 * lc;
                if (col     > row0) sc[nf][0] = -INFINITY;
                if (col + 1 > row0) sc[nf][1] = -INFINITY;
                if (col     > row1) sc[nf][2] = -INFINITY;
                if (col + 1 > row1) sc[nf][3] = -INFINITY;
            }
        }

        // ---- online softmax (rows lr and lr+8, groups of 4 lanes) ----
        float tm0 = -INFINITY, tm1 = -INFINITY;
        #pragma unroll
        for (int nf = 0; nf < 8; nf++) {
            tm0 = fmaxf(tm0, fmaxf(sc[nf][0], sc[nf][1]));
            tm1 = fmaxf(tm1, fmaxf(sc[nf][2], sc[nf][3]));
        }
        #pragma unroll
        for (int off = 1; off < 4; off <<= 1) {
            tm0 = fmaxf(tm0, __shfl_xor_sync(0xffffffffu, tm0, off));
            tm1 = fmaxf(tm1, __shfl_xor_sync(0xffffffffu, tm1, off));
        }
        float mn0 = fmaxf(m0, tm0), mn1 = fmaxf(m1, tm1);
        float corr0 = __expf(m0 - mn0), corr1 = __expf(m1 - mn1);
        m0 = mn0; m1 = mn1;

        float ls0 = 0.f, ls1 = 0.f;
        #pragma unroll
        for (int nf = 0; nf < 8; nf++) {
            sc[nf][0] = __expf(sc[nf][0] - mn0);
            sc[nf][1] = __expf(sc[nf][1] - mn0);
            sc[nf][2] = __expf(sc[nf][2] - mn1);
            sc[nf][3] = __expf(sc[nf][3] - mn1);
            ls0 += sc[nf][0] + sc[nf][1];
            ls1 += sc[nf][2] + sc[nf][3];
        }
        #pragma unroll
        for (int off = 1; off < 4; off <<= 1) {
            ls0 += __shfl_xor_sync(0xffffffffu, ls0, off);
            ls1 += __shfl_xor_sync(0xffffffffu, ls1, off);
        }
        l0 = l0 * corr0 + ls0;
        l1 = l1 * corr1 + ls1;
        #pragma unroll
        for (int nf = 0; nf < 8; nf++) {
            accO[nf][0] *= corr0; accO[nf][1] *= corr0;
            accO[nf][2] *= corr1; accO[nf][3] *= corr1;
        }

        // ---- pack P fragments (A-operand layout for PV) ----
        uint32_t Ph[4][4], Pl[4][4];
        #pragma unroll
        for (int kc = 0; kc < 4; kc++) {
            int na = 2 * kc, nb = 2 * kc + 1;
            Ph[kc][0] = pack2f(sc[na][0], sc[na][1]);
            Ph[kc][1] = pack2f(sc[na][2], sc[na][3]);
            Ph[kc][2] = pack2f(sc[nb][0], sc[nb][1]);
            Ph[kc][3] = pack2f(sc[nb][2], sc[nb][3]);
            Pl[kc][0] = pack2f_lo(sc[na][0], sc[na][1]);
            Pl[kc][1] = pack2f_lo(sc[na][2], sc[na][3]);
            Pl[kc][2] = pack2f_lo(sc[nb][0], sc[nb][1]);
            Pl[kc][3] = pack2f_lo(sc[nb][2], sc[nb][3]);
        }

        // ---- O += P V (3-term) ----
        #pragma unroll
        for (int nfp = 0; nfp < 4; nfp++) {
            #pragma unroll
            for (int kc = 0; kc < 4; kc++) {
                uint32_t vh[4], vl[4];
                ldsm4t(vh[0], vh[1], vh[2], vh[3], sVb + voff[nfp][kc]);
                ldsm4t(vl[0], vl[1], vl[2], vl[3], sVb + APLB_ + voff[nfp][kc]);
                int nf0 = nfp * 2, nf1 = nf0 + 1;
                mma_bf16(accO[nf0], Pl[kc], vh[0], vh[1]);
                mma_bf16(accO[nf0], Ph[kc], vl[0], vl[1]);
                mma_bf16(accO[nf0], Ph[kc], vh[0], vh[1]);
                mma_bf16(accO[nf1], Pl[kc], vh[2], vh[3]);
                mma_bf16(accO[nf1], Ph[kc], vl[2], vl[3]);
                mma_bf16(accO[nf1], Ph[kc], vh[2], vh[3]);
            }
        }
    }

    float inv0 = 1.f / l0, inv1 = 1.f / l1;
    int row0 = q0 + w * 16 + lr;
    #pragma unroll
    for (int nf = 0; nf < 8; nf++) {
        int col = nf * 8 + 2 * lc;
        *(float2*)(o + base + (size_t)row0 * DIM_ + col) =
            make_float2(accO[nf][0] * inv0, accO[nf][1] * inv0);
        *(float2*)(o + base + (size_t)(row0 + 8) * DIM_ + col) =
            make_float2(accO[nf][2] * inv1, accO[nf][3] * inv1);
    }
}

// ---------------------------------------------------------------------------
// SwiGLU elementwise
// ---------------------------------------------------------------------------
__global__ void silu_mul_kernel(float* __restrict__ g1, const float* __restrict__ g3) {
    int idx = blockIdx.x * blockDim.x + threadIdx.x;
    float a = g1[idx];
    float b = g3[idx];
    g1[idx] = a / (1.f + __expf(-a)) * b;
}

// ---------------------------------------------------------------------------
// Host orchestration
// ---------------------------------------------------------------------------
extern "C" void kernel_launch(void* const* d_in, const int* in_sizes, int n_in,
                              void* d_out, int out_size) {
    const int*   tokens      = (const int*)  d_in[0];
    const float* tok_emb     = (const float*)d_in[1];
    const float* wq          = (const float*)d_in[2];
    const float* wk          = (const float*)d_in[3];
    const float* wv          = (const float*)d_in[4];
    const float* wo          = (const float*)d_in[5];
    const float* w1          = (const float*)d_in[6];
    const float* w2          = (const float*)d_in[7];
    const float* w3          = (const float*)d_in[8];
    const float* attn_norm_w = (const float*)d_in[9];
    const float* ffn_norm_w  = (const float*)d_in[10];
    const float* norm_w      = (const float*)d_in[11];
    const float* out_w       = (const float*)d_in[12];

    float *h, *xn, *q, *k, *v, *o, *g1, *g3;
    cudaGetSymbolAddress((void**)&h,  g_h);
    cudaGetSymbolAddress((void**)&xn, g_xn);
    cudaGetSymbolAddress((void**)&q,  g_q);
    cudaGetSymbolAddress((void**)&k,  g_k);
    cudaGetSymbolAddress((void**)&v,  g_v);
    cudaGetSymbolAddress((void**)&o,  g_o);
    cudaGetSymbolAddress((void**)&g1, g_g1);
    cudaGetSymbolAddress((void**)&g3, g_g3);

    embed_kernel<<<T_, 256>>>(tokens, tok_emb, h);

    dim3 gDD (DIM_   / 128, T_ / 128);
    dim3 gDF (HFF_   / 128, T_ / 128);
    dim3 gDV (VOCAB_ / 128, T_ / 128);

    for (int l = 0; l < NL_; l++) {
        const float* wq_l = wq + (size_t)l * DIM_ * DIM_;
        const float* wk_l = wk + (size_t)l * DIM_ * DIM_;
        const float* wv_l = wv + (size_t)l * DIM_ * DIM_;
        const float* wo_l = wo + (size_t)l * DIM_ * DIM_;
        const float* w1_l = w1 + (size_t)l * HFF_ * DIM_;
        const float* w2_l = w2 + (size_t)l * DIM_ * HFF_;
        const float* w3_l = w3 + (size_t)l * HFF_ * DIM_;

        rmsnorm_kernel<<<T_, 256>>>(h, attn_norm_w + (size_t)l * DIM_, xn);
        tgemm_nt<false><<<gDD, 256>>>(xn, wq_l, q, T_, DIM_, DIM_);
        tgemm_nt<false><<<gDD, 256>>>(xn, wk_l, k, T_, DIM_, DIM_);
        tgemm_nt<false><<<gDD, 256>>>(xn, wv_l, v, T_, DIM_, DIM_);
        rope_kernel<<<(T_ * 512) / 256, 256>>>(q, k);
        attn_mma_kernel<<<dim3(S_ / 64, NH_, B_), 128>>>(q, k, v, o);
        tgemm_nt<true ><<<gDD, 256>>>(o, wo_l, h, T_, DIM_, DIM_);

        rmsnorm_kernel<<<T_, 256>>>(h, ffn_norm_w + (size_t)l * DIM_, xn);
        tgemm_nt<false><<<gDF, 256>>>(xn, w1_l, g1, T_, HFF_, DIM_);
        tgemm_nt<false><<<gDF, 256>>>(xn, w3_l, g3, T_, HFF_, DIM_);
        silu_mul_kernel<<<(T_ * HFF_) / 256, 256>>>(g1, g3);
        tgemm_nt<true ><<<gDD, 256>>>(g1, w2_l, h, T_, DIM_, HFF_);
    }

    rmsnorm_kernel<<<T_, 256>>>(h, norm_w, xn);
    tgemm_nt<false><<<gDV, 256>>>(xn, out_w, (float*)d_out, T_, VOCAB_, DIM_);
}